// round 9
// baseline (speedup 1.0000x reference)
#include <cuda_runtime.h>
#include <cuda_fp16.h>
#include <cstdint>

#define R_ROWS 264384                    // B*L*J = 64*243*17
#define NCOPY  64                        // striped BN accumulator copies
#define MTILES ((R_ROWS + 127) / 128)    // 2066

// ---------------- scratch (device globals: no allocations allowed) ----------
__device__ __half g_xm[(long long)R_ROWS * 256];    // adj-mixed x (half)
__device__ __half g_hh[(long long)R_ROWS * 256];    // h = relu(xm@Wc+bc) (half)
__device__ __half g_hn[(long long)R_ROWS * 256];    // LN output (half)
__device__ __half g_midh[(long long)R_ROWS * 512];  // MLP hidden (half)
__device__ __half g_Wch[256 * 256];                 // h(w1+w2)   [o][d] K-major
__device__ __half g_W1h[512 * 256];                 // h(mlp_w1)  [h][o] K-major
__device__ __half g_W2h[256 * 512];                 // h(mlp_w2)  [o][h] K-major
__device__ float  g_bc[256];                        // b1+b2
__device__ float  g_stats[NCOPY * 512];             // [sum|sumsq] per copy
__device__ float  g_sc[256];                        // BN scale
__device__ float  g_tsh[256];                       // BN shift

// ---------------- helpers ----------------------------------------------------
__device__ __forceinline__ uint32_t smem_u32(const void* p) {
    uint32_t a;
    asm("{ .reg .u64 t; cvta.to.shared.u64 t, %1; cvt.u32.u64 %0, t; }"
        : "=r"(a) : "l"(p));
    return a;
}
__device__ __forceinline__ void mma_f16(float* d, const uint32_t* a, const uint32_t* b) {
    asm volatile(
        "mma.sync.aligned.m16n8k16.row.col.f32.f16.f16.f32 "
        "{%0,%1,%2,%3}, {%4,%5,%6,%7}, {%8,%9}, {%0,%1,%2,%3};\n"
        : "+f"(d[0]), "+f"(d[1]), "+f"(d[2]), "+f"(d[3])
        : "r"(a[0]), "r"(a[1]), "r"(a[2]), "r"(a[3]), "r"(b[0]), "r"(b[1]));
}
__device__ __forceinline__ void cp16(uint32_t dst, const void* src) {
    asm volatile("cp.async.cg.shared.global [%0], [%1], 16;" :: "r"(dst), "l"(src));
}
__device__ __forceinline__ void cp16z(uint32_t dst, const void* src, unsigned pred16) {
    asm volatile("cp.async.cg.shared.global [%0], [%1], 16, %2;"
                 :: "r"(dst), "l"(src), "r"(pred16));
}

// ---------------- K0: weight prep (half) + stats zeroing ---------------------
__global__ __launch_bounds__(256) void k_prep(
        const float* __restrict__ w1, const float* __restrict__ b1,
        const float* __restrict__ w2, const float* __restrict__ b2,
        const float* __restrict__ mw1, const float* __restrict__ mw2) {
    int i = blockIdx.x * 256 + threadIdx.x;   // 0..131071
    g_W1h[i] = __float2half_rn(mw1[i]);       // native [512,256] K-major
    g_W2h[i] = __float2half_rn(mw2[i]);       // native [256,512] K-major
    if (i < 256 * 256) g_Wch[i] = __float2half_rn(w1[i] + w2[i]);
    if (i < NCOPY * 512) g_stats[i] = 0.f;
    if (i < 256) g_bc[i] = b1[i] + b2[i];
}

// ---------------- K1: per-frame adjacency mix on x, fp32 -> half -------------
// xm[f,i,:] = sum_j adj[i,j] * x[f,j,:]   (adj symmetric)
__global__ __launch_bounds__(256) void k_xmix(const float* __restrict__ x,
                                              const float* __restrict__ adj) {
    __shared__ float sadj[17 * 17];
    int f = blockIdx.x;
    int o = threadIdx.x;
    for (int i = o; i < 289; i += 256) sadj[i] = adj[i];
    __syncthreads();
    const float* xp = x + (size_t)f * 17 * 256 + o;
    float v[17];
#pragma unroll
    for (int j = 0; j < 17; j++) v[j] = xp[(size_t)j * 256];
    __half* op = g_xm + (size_t)f * 17 * 256 + o;
#pragma unroll
    for (int i = 0; i < 17; i++) {
        float g = 0.f;
#pragma unroll
        for (int j = 0; j < 17; j++) g = fmaf(sadj[i * 17 + j], v[j], g);
        op[(size_t)i * 256] = __float2half_rn(g);
    }
}

// ---------- fp16 mma GEMM: C[M,N] = A[M,K] @ Bw[N,K]^T + bias ----------------
// CTA 128x256, BK=32 (2 k16-steps), 256 thr (8 warps: 2M x 4N), warp 64x64.
// 4-stage cp.async pipeline, one __syncthreads per chunk.
// STATS: epilogue accumulates per-channel sum/sumsq via smem -> striped atomics.
#define LDH   40
#define ASTG  (128 * LDH * 2)             // 10240 B
#define BSTG  (256 * LDH * 2)             // 20480 B
#define STG   (ASTG + BSTG)               // 30720 B
#define SMEM_DYN (4 * STG)                // 122880 B

template <bool RELU, bool OUT_HALF, bool STATS>
__global__ __launch_bounds__(256, 1) void k_mma(
        const __half* __restrict__ A, const __half* __restrict__ Bw,
        const float* __restrict__ bias, void* __restrict__ Cv,
        int M, int N, int K) {
    extern __shared__ char dsm[];
    __shared__ float s_bias[256];
    __shared__ float s_st[512];

    const int tid = threadIdx.x;
    const int wid = tid >> 5, lane = tid & 31;
    const int wm = wid >> 2, wn = wid & 3;      // warp grid 2x4
    const int row0 = blockIdx.y * 128;
    const int n0 = blockIdx.x * 256;
    const int NC = K >> 5;

    const uint32_t sb = smem_u32(dsm);

    s_bias[tid] = bias[n0 + tid];
    if (STATS) { s_st[tid] = 0.f; s_st[tid + 256] = 0.f; }

    // chunk loader: A 128 rows x 32 halves (4 x 16B segs), B 256 rows x 4 segs
    auto load_chunk = [&](int ck, int st) {
        const int k0 = ck << 5;
        const uint32_t sA = sb + (uint32_t)st * STG;
        const uint32_t sB = sA + ASTG;
#pragma unroll
        for (int j = 0; j < 2; j++) {           // 512 segs
            int id = tid + (j << 8);
            int r = id >> 2, seg = id & 3;
            int gr = row0 + r;
            const __half* gp =
                A + (size_t)(gr < M ? gr : (M - 1)) * K + k0 + (seg << 3);
            cp16z(sA + (uint32_t)(r * LDH + (seg << 3)) * 2u, gp,
                  gr < M ? 16u : 0u);
        }
#pragma unroll
        for (int j = 0; j < 4; j++) {           // 1024 segs
            int id = tid + (j << 8);
            int r = id >> 2, seg = id & 3;
            const __half* gp = Bw + (size_t)(n0 + r) * K + k0 + (seg << 3);
            cp16(sB + (uint32_t)(r * LDH + (seg << 3)) * 2u, gp);
        }
        asm volatile("cp.async.commit_group;" ::: "memory");
    };

    float acc[4][8][4];
#pragma unroll
    for (int i = 0; i < 4; i++)
#pragma unroll
        for (int j = 0; j < 8; j++)
#pragma unroll
            for (int r = 0; r < 4; r++) acc[i][j][r] = 0.f;

    load_chunk(0, 0);
    load_chunk(1, 1);
    load_chunk(2, 2);

    const int qr = lane >> 2, qc = lane & 3;    // quad row / col
    for (int c = 0; c < NC; c++) {
        if (c + 2 < NC)
            asm volatile("cp.async.wait_group 2;" ::: "memory");
        else if (c + 1 < NC)
            asm volatile("cp.async.wait_group 1;" ::: "memory");
        else
            asm volatile("cp.async.wait_group 0;" ::: "memory");
        __syncthreads();   // chunk c visible; all warps done reading c-1

        const int st = c & 3;
        const uint32_t bA = sb + st * STG + ((wm * 64 + qr) * LDH) * 2u + qc * 4u;
        const uint32_t bB = sb + st * STG + ASTG
                          + ((wn * 64 + qr) * LDH) * 2u + qc * 4u;
#pragma unroll
        for (int s = 0; s < 2; s++) {           // 2 k-steps of 16
            const uint32_t ks = s * 32u;        // 16 halves
            uint32_t af[4][4], bf[8][2];
#pragma unroll
            for (int mt = 0; mt < 4; mt++) {
                uint32_t base = bA + ks + (uint32_t)(mt * 16 * LDH) * 2u;
                asm volatile("ld.shared.b32 %0, [%1];" : "=r"(af[mt][0]) : "r"(base));
                asm volatile("ld.shared.b32 %0, [%1];" : "=r"(af[mt][1]) : "r"(base + 8u * LDH * 2u));
                asm volatile("ld.shared.b32 %0, [%1];" : "=r"(af[mt][2]) : "r"(base + 16u));
                asm volatile("ld.shared.b32 %0, [%1];" : "=r"(af[mt][3]) : "r"(base + 8u * LDH * 2u + 16u));
            }
#pragma unroll
            for (int nt = 0; nt < 8; nt++) {
                uint32_t base = bB + ks + (uint32_t)(nt * 8 * LDH) * 2u;
                asm volatile("ld.shared.b32 %0, [%1];" : "=r"(bf[nt][0]) : "r"(base));
                asm volatile("ld.shared.b32 %0, [%1];" : "=r"(bf[nt][1]) : "r"(base + 16u));
            }
#pragma unroll
            for (int mt = 0; mt < 4; mt++)
#pragma unroll
                for (int nt = 0; nt < 8; nt++)
                    mma_f16(acc[mt][nt], af[mt], bf[nt]);
        }
        // prefetch chunk c+3 into the freed stage ((c+3)&3 == (c-1)&3)
        if (c + 3 < NC) load_chunk(c + 3, (c + 3) & 3);
    }

    // epilogue: bias (+relu) (+BN partial stats), fp32/half stores
    float stx[8][4];
    if (STATS) {
#pragma unroll
        for (int nt = 0; nt < 8; nt++)
#pragma unroll
            for (int r = 0; r < 4; r++) stx[nt][r] = 0.f;
    }
#pragma unroll
    for (int mt = 0; mt < 4; mt++) {
        int r0 = row0 + wm * 64 + mt * 16 + qr;
        bool v0ok = r0 < M, v2ok = r0 + 8 < M;
#pragma unroll
        for (int nt = 0; nt < 8; nt++) {
            int cc = wn * 64 + nt * 8 + qc * 2;
            float b0 = s_bias[cc], b1 = s_bias[cc + 1];
            float v0 = acc[mt][nt][0] + b0, v1 = acc[mt][nt][1] + b1;
            float v2 = acc[mt][nt][2] + b0, v3 = acc[mt][nt][3] + b1;
            if (RELU) {
                v0 = fmaxf(v0, 0.f); v1 = fmaxf(v1, 0.f);
                v2 = fmaxf(v2, 0.f); v3 = fmaxf(v3, 0.f);
            }
            if (STATS) {
                if (v0ok) {
                    stx[nt][0] += v0; stx[nt][1] += v1;
                    stx[nt][2] = fmaf(v0, v0, stx[nt][2]);
                    stx[nt][3] = fmaf(v1, v1, stx[nt][3]);
                }
                if (v2ok) {
                    stx[nt][0] += v2; stx[nt][1] += v3;
                    stx[nt][2] = fmaf(v2, v2, stx[nt][2]);
                    stx[nt][3] = fmaf(v3, v3, stx[nt][3]);
                }
            }
            if (OUT_HALF) {
                __half* C = (__half*)Cv;
                if (v0ok)
                    *(__half2*)(C + (size_t)r0 * N + n0 + cc) = __floats2half2_rn(v0, v1);
                if (v2ok)
                    *(__half2*)(C + (size_t)(r0 + 8) * N + n0 + cc) = __floats2half2_rn(v2, v3);
            } else {
                float* C = (float*)Cv;
                if (v0ok)
                    *(float2*)(C + (size_t)r0 * N + n0 + cc) = make_float2(v0, v1);
                if (v2ok)
                    *(float2*)(C + (size_t)(r0 + 8) * N + n0 + cc) = make_float2(v2, v3);
            }
        }
    }
    if (STATS) {
#pragma unroll
        for (int nt = 0; nt < 8; nt++) {
            int cc = wn * 64 + nt * 8 + qc * 2;
            atomicAdd(&s_st[cc], stx[nt][0]);
            atomicAdd(&s_st[cc + 1], stx[nt][1]);
            atomicAdd(&s_st[256 + cc], stx[nt][2]);
            atomicAdd(&s_st[256 + cc + 1], stx[nt][3]);
        }
        __syncthreads();
        float* gs = g_stats + (size_t)(blockIdx.y & (NCOPY - 1)) * 512;
        atomicAdd(gs + tid, s_st[tid]);
        atomicAdd(gs + 256 + tid, s_st[256 + tid]);
    }
}

// ---------------- K3: finalize BN statistics ---------------------------------
__global__ __launch_bounds__(256) void k_finstats(const float* __restrict__ bg,
                                                  const float* __restrict__ bb) {
    int o = threadIdx.x;
    float s = 0.f, s2 = 0.f;
#pragma unroll 8
    for (int c = 0; c < NCOPY; c++) {
        s += g_stats[c * 512 + o];
        s2 += g_stats[c * 512 + 256 + o];
    }
    const float inv = 1.f / (float)R_ROWS;
    float mu = s * inv;
    float var = fmaxf(s2 * inv - mu * mu, 0.f);
    float rs = rsqrtf(var + 1e-5f);
    float sc = rs * bg[o];
    g_sc[o] = sc;
    g_tsh[o] = bb[o] - mu * sc;
}

// ---------------- K4: BN apply + LayerNorm (h half -> hn half) ---------------
__global__ __launch_bounds__(256) void k_bnln(const float* __restrict__ lg,
                                              const float* __restrict__ lb) {
    int row = blockIdx.x * 8 + (threadIdx.x >> 5);
    int lane = threadIdx.x & 31;
    const __half2* hp = (const __half2*)(g_hh + (size_t)row * 256);
    float v[8];
    float s = 0.f, s2 = 0.f;
#pragma unroll
    for (int i = 0; i < 4; i++) {
        int k2 = lane + 32 * i;                 // half2 index (0..127)
        float2 xv = __half22float2(hp[k2]);
        float x0 = fmaf(xv.x, g_sc[2 * k2], g_tsh[2 * k2]);
        float x1 = fmaf(xv.y, g_sc[2 * k2 + 1], g_tsh[2 * k2 + 1]);
        v[2 * i] = x0; v[2 * i + 1] = x1;
        s += x0 + x1;
        s2 = fmaf(x0, x0, s2);
        s2 = fmaf(x1, x1, s2);
    }
#pragma unroll
    for (int off = 16; off; off >>= 1) {
        s += __shfl_xor_sync(0xffffffffu, s, off);
        s2 += __shfl_xor_sync(0xffffffffu, s2, off);
    }
    float mu = s * (1.f / 256.f);
    float var = fmaxf(s2 * (1.f / 256.f) - mu * mu, 0.f);
    float rs = rsqrtf(var + 1e-5f);
    __half2* op = (__half2*)(g_hn + (size_t)row * 256);
#pragma unroll
    for (int i = 0; i < 4; i++) {
        int k2 = lane + 32 * i;
        float y0 = fmaf((v[2 * i] - mu) * rs, lg[2 * k2], lb[2 * k2]);
        float y1 = fmaf((v[2 * i + 1] - mu) * rs, lg[2 * k2 + 1], lb[2 * k2 + 1]);
        op[k2] = __floats2half2_rn(y0, y1);
    }
}

// ---------------- host side --------------------------------------------------
extern "C" void kernel_launch(void* const* d_in, const int* in_sizes, int n_in,
                              void* d_out, int out_size) {
    (void)in_sizes; (void)n_in; (void)out_size;
    const float* x   = (const float*)d_in[0];
    const float* adj = (const float*)d_in[1];
    const float* w1  = (const float*)d_in[2];
    const float* b1  = (const float*)d_in[3];
    const float* w2  = (const float*)d_in[4];
    const float* b2  = (const float*)d_in[5];
    const float* bng = (const float*)d_in[6];
    const float* bnb = (const float*)d_in[7];
    const float* lng = (const float*)d_in[8];
    const float* lnb = (const float*)d_in[9];
    const float* mw1 = (const float*)d_in[10];
    const float* mb1 = (const float*)d_in[11];
    const float* mw2 = (const float*)d_in[12];
    const float* mb2 = (const float*)d_in[13];
    float* out = (float*)d_out;

    void *pxm = 0, *phh = 0, *phn = 0, *pm = 0, *pWc = 0, *pW1 = 0, *pW2 = 0, *pbc = 0;
    cudaGetSymbolAddress(&pxm, g_xm);
    cudaGetSymbolAddress(&phh, g_hh);
    cudaGetSymbolAddress(&phn, g_hn);
    cudaGetSymbolAddress(&pm, g_midh);
    cudaGetSymbolAddress(&pWc, g_Wch);
    cudaGetSymbolAddress(&pW1, g_W1h);
    cudaGetSymbolAddress(&pW2, g_W2h);
    cudaGetSymbolAddress(&pbc, g_bc);

    cudaFuncSetAttribute(k_mma<true, true, true>,
                         cudaFuncAttributeMaxDynamicSharedMemorySize, SMEM_DYN);
    cudaFuncSetAttribute(k_mma<true, true, false>,
                         cudaFuncAttributeMaxDynamicSharedMemorySize, SMEM_DYN);
    cudaFuncSetAttribute(k_mma<false, false, false>,
                         cudaFuncAttributeMaxDynamicSharedMemorySize, SMEM_DYN);

    k_prep<<<512, 256>>>(w1, b1, w2, b2, mw1, mw2);
    // xm = adj @ x (per frame), half
    k_xmix<<<R_ROWS / 17, 256>>>(x, adj);
    // h (half) = relu(xm @ Wc^T + bc), + BN partial stats in epilogue
    k_mma<true, true, true><<<dim3(1, MTILES), 256, SMEM_DYN>>>(
        (const __half*)pxm, (const __half*)pWc, (const float*)pbc,
        (void*)phh, R_ROWS, 256, 256);
    k_finstats<<<1, 256>>>(bng, bnb);
    // hn (half) = LN(BN(h))
    k_bnln<<<R_ROWS / 8, 256>>>(lng, lnb);
    // mid (half) = relu(hn @ mlp_w1^T + mb1)
    k_mma<true, true, false><<<dim3(2, MTILES), 256, SMEM_DYN>>>(
        (const __half*)phn, (const __half*)pW1, mb1, (void*)pm, R_ROWS, 512, 256);
    // out (fp32) = mid @ mlp_w2^T + mb2
    k_mma<false, false, false><<<dim3(1, MTILES), 256, SMEM_DYN>>>(
        (const __half*)pm, (const __half*)pW2, mb2, (void*)out, R_ROWS, 256, 512);
}

// round 10
// speedup vs baseline: 1.2448x; 1.2448x over previous
#include <cuda_runtime.h>
#include <cuda_fp16.h>
#include <cstdint>

#define R_ROWS 264384                    // B*L*J = 64*243*17
#define NCOPY  64                        // striped BN accumulator copies
#define MTILES ((R_ROWS + 127) / 128)    // 2066

// ---------------- scratch (device globals: no allocations allowed) ----------
__device__ __half g_xm[(long long)R_ROWS * 256];    // adj-mixed x (half)
__device__ __half g_hh[(long long)R_ROWS * 256];    // h = relu(xm@Wc+bc) (half)
__device__ __half g_hn[(long long)R_ROWS * 256];    // LN output (half)
__device__ __half g_midh[(long long)R_ROWS * 512];  // MLP hidden (half)
__device__ __half g_Wch[256 * 256];                 // h(w1+w2)   [o][d] K-major
__device__ __half g_W1h[512 * 256];                 // h(mlp_w1)  [h][o] K-major
__device__ __half g_W2h[256 * 512];                 // h(mlp_w2)  [o][h] K-major
__device__ float  g_bc[256];                        // b1+b2
__device__ float  g_stats[NCOPY * 512];             // [sum|sumsq] per copy
__device__ float  g_sc[256];                        // BN scale
__device__ float  g_tsh[256];                       // BN shift

// ---------------- helpers ----------------------------------------------------
__device__ __forceinline__ uint32_t smem_u32(const void* p) {
    uint32_t a;
    asm("{ .reg .u64 t; cvta.to.shared.u64 t, %1; cvt.u32.u64 %0, t; }"
        : "=r"(a) : "l"(p));
    return a;
}
__device__ __forceinline__ void mma_f16(float* d, const uint32_t* a, const uint32_t* b) {
    asm volatile(
        "mma.sync.aligned.m16n8k16.row.col.f32.f16.f16.f32 "
        "{%0,%1,%2,%3}, {%4,%5,%6,%7}, {%8,%9}, {%0,%1,%2,%3};\n"
        : "+f"(d[0]), "+f"(d[1]), "+f"(d[2]), "+f"(d[3])
        : "r"(a[0]), "r"(a[1]), "r"(a[2]), "r"(a[3]), "r"(b[0]), "r"(b[1]));
}
__device__ __forceinline__ void cp16(uint32_t dst, const void* src) {
    asm volatile("cp.async.cg.shared.global [%0], [%1], 16;" :: "r"(dst), "l"(src));
}
__device__ __forceinline__ void cp16z(uint32_t dst, const void* src, unsigned pred16) {
    asm volatile("cp.async.cg.shared.global [%0], [%1], 16, %2;"
                 :: "r"(dst), "l"(src), "r"(pred16));
}

// ---------------- K0: weight prep (half) + stats zeroing ---------------------
__global__ __launch_bounds__(256) void k_prep(
        const float* __restrict__ w1, const float* __restrict__ b1,
        const float* __restrict__ w2, const float* __restrict__ b2,
        const float* __restrict__ mw1, const float* __restrict__ mw2) {
    int i = blockIdx.x * 256 + threadIdx.x;   // 0..131071
    g_W1h[i] = __float2half_rn(mw1[i]);       // native [512,256] K-major
    g_W2h[i] = __float2half_rn(mw2[i]);       // native [256,512] K-major
    if (i < 256 * 256) g_Wch[i] = __float2half_rn(w1[i] + w2[i]);
    if (i < NCOPY * 512) g_stats[i] = 0.f;
    if (i < 256) g_bc[i] = b1[i] + b2[i];
}

// ---------------- K1: per-frame adjacency mix on x, fp32 -> half -------------
// xm[f,i,:] = sum_j adj[i,j] * x[f,j,:]   (adj symmetric)
__global__ __launch_bounds__(256) void k_xmix(const float* __restrict__ x,
                                              const float* __restrict__ adj) {
    __shared__ float sadj[17 * 17];
    int f = blockIdx.x;
    int o = threadIdx.x;
    for (int i = o; i < 289; i += 256) sadj[i] = adj[i];
    __syncthreads();
    const float* xp = x + (size_t)f * 17 * 256 + o;
    float v[17];
#pragma unroll
    for (int j = 0; j < 17; j++) v[j] = xp[(size_t)j * 256];
    __half* op = g_xm + (size_t)f * 17 * 256 + o;
#pragma unroll
    for (int i = 0; i < 17; i++) {
        float g = 0.f;
#pragma unroll
        for (int j = 0; j < 17; j++) g = fmaf(sadj[i * 17 + j], v[j], g);
        op[(size_t)i * 256] = __float2half_rn(g);
    }
}

// ---------- fp16 mma GEMM: C[M,N] = A[M,K] @ Bw[N,K]^T + bias ----------------
// CTA 128x256, BK=32 (2 k16-steps), 256 thr (8 warps: 2M x 4N), warp 64x64.
// 4-stage cp.async pipeline, one __syncthreads per chunk.  (R8-proven loop.)
#define LDH   40
#define ASTG  (128 * LDH * 2)             // 10240 B
#define BSTG  (256 * LDH * 2)             // 20480 B
#define STG   (ASTG + BSTG)               // 30720 B
#define SMEM_DYN (4 * STG)                // 122880 B

template <bool RELU, bool OUT_HALF>
__global__ __launch_bounds__(256, 1) void k_mma(
        const __half* __restrict__ A, const __half* __restrict__ Bw,
        const float* __restrict__ bias, void* __restrict__ Cv,
        int M, int N, int K) {
    extern __shared__ char dsm[];
    __shared__ float s_bias[256];

    const int tid = threadIdx.x;
    const int wid = tid >> 5, lane = tid & 31;
    const int wm = wid >> 2, wn = wid & 3;      // warp grid 2x4
    const int row0 = blockIdx.y * 128;
    const int n0 = blockIdx.x * 256;
    const int NC = K >> 5;

    const uint32_t sb = smem_u32(dsm);

    s_bias[tid] = bias[n0 + tid];

    // chunk loader: A 128 rows x 32 halves (4 x 16B segs), B 256 rows x 4 segs
    auto load_chunk = [&](int ck, int st) {
        const int k0 = ck << 5;
        const uint32_t sA = sb + (uint32_t)st * STG;
        const uint32_t sB = sA + ASTG;
#pragma unroll
        for (int j = 0; j < 2; j++) {           // 512 segs
            int id = tid + (j << 8);
            int r = id >> 2, seg = id & 3;
            int gr = row0 + r;
            const __half* gp =
                A + (size_t)(gr < M ? gr : (M - 1)) * K + k0 + (seg << 3);
            cp16z(sA + (uint32_t)(r * LDH + (seg << 3)) * 2u, gp,
                  gr < M ? 16u : 0u);
        }
#pragma unroll
        for (int j = 0; j < 4; j++) {           // 1024 segs
            int id = tid + (j << 8);
            int r = id >> 2, seg = id & 3;
            const __half* gp = Bw + (size_t)(n0 + r) * K + k0 + (seg << 3);
            cp16(sB + (uint32_t)(r * LDH + (seg << 3)) * 2u, gp);
        }
        asm volatile("cp.async.commit_group;" ::: "memory");
    };

    float acc[4][8][4];
#pragma unroll
    for (int i = 0; i < 4; i++)
#pragma unroll
        for (int j = 0; j < 8; j++)
#pragma unroll
            for (int r = 0; r < 4; r++) acc[i][j][r] = 0.f;

    load_chunk(0, 0);
    load_chunk(1, 1);
    load_chunk(2, 2);

    const int qr = lane >> 2, qc = lane & 3;    // quad row / col
    for (int c = 0; c < NC; c++) {
        if (c + 2 < NC)
            asm volatile("cp.async.wait_group 2;" ::: "memory");
        else if (c + 1 < NC)
            asm volatile("cp.async.wait_group 1;" ::: "memory");
        else
            asm volatile("cp.async.wait_group 0;" ::: "memory");
        __syncthreads();   // chunk c visible; all warps done reading c-1

        const int st = c & 3;
        const uint32_t bA = sb + st * STG + ((wm * 64 + qr) * LDH) * 2u + qc * 4u;
        const uint32_t bB = sb + st * STG + ASTG
                          + ((wn * 64 + qr) * LDH) * 2u + qc * 4u;
#pragma unroll
        for (int s = 0; s < 2; s++) {           // 2 k-steps of 16
            const uint32_t ks = s * 32u;        // 16 halves
            uint32_t af[4][4], bf[8][2];
#pragma unroll
            for (int mt = 0; mt < 4; mt++) {
                uint32_t base = bA + ks + (uint32_t)(mt * 16 * LDH) * 2u;
                asm volatile("ld.shared.b32 %0, [%1];" : "=r"(af[mt][0]) : "r"(base));
                asm volatile("ld.shared.b32 %0, [%1];" : "=r"(af[mt][1]) : "r"(base + 8u * LDH * 2u));
                asm volatile("ld.shared.b32 %0, [%1];" : "=r"(af[mt][2]) : "r"(base + 16u));
                asm volatile("ld.shared.b32 %0, [%1];" : "=r"(af[mt][3]) : "r"(base + 8u * LDH * 2u + 16u));
            }
#pragma unroll
            for (int nt = 0; nt < 8; nt++) {
                uint32_t base = bB + ks + (uint32_t)(nt * 8 * LDH) * 2u;
                asm volatile("ld.shared.b32 %0, [%1];" : "=r"(bf[nt][0]) : "r"(base));
                asm volatile("ld.shared.b32 %0, [%1];" : "=r"(bf[nt][1]) : "r"(base + 16u));
            }
#pragma unroll
            for (int mt = 0; mt < 4; mt++)
#pragma unroll
                for (int nt = 0; nt < 8; nt++)
                    mma_f16(acc[mt][nt], af[mt], bf[nt]);
        }
        // prefetch chunk c+3 into the freed stage ((c+3)&3 == (c-1)&3)
        if (c + 3 < NC) load_chunk(c + 3, (c + 3) & 3);
    }

    // epilogue: bias (+relu), fp32 or half stores
#pragma unroll
    for (int mt = 0; mt < 4; mt++) {
        int r0 = row0 + wm * 64 + mt * 16 + qr;
#pragma unroll
        for (int nt = 0; nt < 8; nt++) {
            int cc = wn * 64 + nt * 8 + qc * 2;
            float b0 = s_bias[cc], b1 = s_bias[cc + 1];
            float v0 = acc[mt][nt][0] + b0, v1 = acc[mt][nt][1] + b1;
            float v2 = acc[mt][nt][2] + b0, v3 = acc[mt][nt][3] + b1;
            if (RELU) {
                v0 = fmaxf(v0, 0.f); v1 = fmaxf(v1, 0.f);
                v2 = fmaxf(v2, 0.f); v3 = fmaxf(v3, 0.f);
            }
            if (OUT_HALF) {
                __half* C = (__half*)Cv;
                if (r0 < M)
                    *(__half2*)(C + (size_t)r0 * N + n0 + cc) = __floats2half2_rn(v0, v1);
                if (r0 + 8 < M)
                    *(__half2*)(C + (size_t)(r0 + 8) * N + n0 + cc) = __floats2half2_rn(v2, v3);
            } else {
                float* C = (float*)Cv;
                if (r0 < M)
                    *(float2*)(C + (size_t)r0 * N + n0 + cc) = make_float2(v0, v1);
                if (r0 + 8 < M)
                    *(float2*)(C + (size_t)(r0 + 8) * N + n0 + cc) = make_float2(v2, v3);
            }
        }
    }
}

// ---------------- K2b: BN partial stats over g_hh (half) ---------------------
// Thread = channel pair; register accumulation; 4 striped global atomics/thread.
#define STATS_CTAS 1024
__global__ __launch_bounds__(256) void k_stats() {
    int tid = threadIdx.x;
    int ch2 = tid & 127;                    // half2 channel index
    int rg = tid >> 7;                      // row group (0/1)
    const __half2* hp = (const __half2*)g_hh;
    float s0 = 0.f, s1 = 0.f, q0 = 0.f, q1 = 0.f;
    for (long long r = (long long)blockIdx.x * 2 + rg; r < R_ROWS;
         r += (long long)STATS_CTAS * 2) {
        float2 v = __half22float2(hp[r * 128 + ch2]);
        s0 += v.x; s1 += v.y;
        q0 = fmaf(v.x, v.x, q0);
        q1 = fmaf(v.y, v.y, q1);
    }
    float* st = g_stats + (size_t)(blockIdx.x & (NCOPY - 1)) * 512;
    atomicAdd(st + 2 * ch2, s0);
    atomicAdd(st + 2 * ch2 + 1, s1);
    atomicAdd(st + 256 + 2 * ch2, q0);
    atomicAdd(st + 256 + 2 * ch2 + 1, q1);
}

// ---------------- K3: finalize BN statistics ---------------------------------
__global__ __launch_bounds__(256) void k_finstats(const float* __restrict__ bg,
                                                  const float* __restrict__ bb) {
    int o = threadIdx.x;
    float s = 0.f, s2 = 0.f;
#pragma unroll 8
    for (int c = 0; c < NCOPY; c++) {
        s += g_stats[c * 512 + o];
        s2 += g_stats[c * 512 + 256 + o];
    }
    const float inv = 1.f / (float)R_ROWS;
    float mu = s * inv;
    float var = fmaxf(s2 * inv - mu * mu, 0.f);
    float rs = rsqrtf(var + 1e-5f);
    float sc = rs * bg[o];
    g_sc[o] = sc;
    g_tsh[o] = bb[o] - mu * sc;
}

// ---------------- K4: BN apply + LayerNorm (h half -> hn half) ---------------
__global__ __launch_bounds__(256) void k_bnln(const float* __restrict__ lg,
                                              const float* __restrict__ lb) {
    int row = blockIdx.x * 8 + (threadIdx.x >> 5);
    int lane = threadIdx.x & 31;
    const __half2* hp = (const __half2*)(g_hh + (size_t)row * 256);
    float v[8];
    float s = 0.f, s2 = 0.f;
#pragma unroll
    for (int i = 0; i < 4; i++) {
        int k2 = lane + 32 * i;                 // half2 index (0..127)
        float2 xv = __half22float2(hp[k2]);
        float x0 = fmaf(xv.x, g_sc[2 * k2], g_tsh[2 * k2]);
        float x1 = fmaf(xv.y, g_sc[2 * k2 + 1], g_tsh[2 * k2 + 1]);
        v[2 * i] = x0; v[2 * i + 1] = x1;
        s += x0 + x1;
        s2 = fmaf(x0, x0, s2);
        s2 = fmaf(x1, x1, s2);
    }
#pragma unroll
    for (int off = 16; off; off >>= 1) {
        s += __shfl_xor_sync(0xffffffffu, s, off);
        s2 += __shfl_xor_sync(0xffffffffu, s2, off);
    }
    float mu = s * (1.f / 256.f);
    float var = fmaxf(s2 * (1.f / 256.f) - mu * mu, 0.f);
    float rs = rsqrtf(var + 1e-5f);
    __half2* op = (__half2*)(g_hn + (size_t)row * 256);
#pragma unroll
    for (int i = 0; i < 4; i++) {
        int k2 = lane + 32 * i;
        float y0 = fmaf((v[2 * i] - mu) * rs, lg[2 * k2], lb[2 * k2]);
        float y1 = fmaf((v[2 * i + 1] - mu) * rs, lg[2 * k2 + 1], lb[2 * k2 + 1]);
        op[k2] = __floats2half2_rn(y0, y1);
    }
}

// ---------------- host side --------------------------------------------------
extern "C" void kernel_launch(void* const* d_in, const int* in_sizes, int n_in,
                              void* d_out, int out_size) {
    (void)in_sizes; (void)n_in; (void)out_size;
    const float* x   = (const float*)d_in[0];
    const float* adj = (const float*)d_in[1];
    const float* w1  = (const float*)d_in[2];
    const float* b1  = (const float*)d_in[3];
    const float* w2  = (const float*)d_in[4];
    const float* b2  = (const float*)d_in[5];
    const float* bng = (const float*)d_in[6];
    const float* bnb = (const float*)d_in[7];
    const float* lng = (const float*)d_in[8];
    const float* lnb = (const float*)d_in[9];
    const float* mw1 = (const float*)d_in[10];
    const float* mb1 = (const float*)d_in[11];
    const float* mw2 = (const float*)d_in[12];
    const float* mb2 = (const float*)d_in[13];
    float* out = (float*)d_out;

    void *pxm = 0, *phh = 0, *phn = 0, *pm = 0, *pWc = 0, *pW1 = 0, *pW2 = 0, *pbc = 0;
    cudaGetSymbolAddress(&pxm, g_xm);
    cudaGetSymbolAddress(&phh, g_hh);
    cudaGetSymbolAddress(&phn, g_hn);
    cudaGetSymbolAddress(&pm, g_midh);
    cudaGetSymbolAddress(&pWc, g_Wch);
    cudaGetSymbolAddress(&pW1, g_W1h);
    cudaGetSymbolAddress(&pW2, g_W2h);
    cudaGetSymbolAddress(&pbc, g_bc);

    cudaFuncSetAttribute(k_mma<true, true>,
                         cudaFuncAttributeMaxDynamicSharedMemorySize, SMEM_DYN);
    cudaFuncSetAttribute(k_mma<false, false>,
                         cudaFuncAttributeMaxDynamicSharedMemorySize, SMEM_DYN);

    k_prep<<<512, 256>>>(w1, b1, w2, b2, mw1, mw2);
    // xm = adj @ x (per frame), half
    k_xmix<<<R_ROWS / 17, 256>>>(x, adj);
    // h (half) = relu(xm @ Wc^T + bc)
    k_mma<true, true><<<dim3(1, MTILES), 256, SMEM_DYN>>>(
        (const __half*)pxm, (const __half*)pWc, (const float*)pbc,
        (void*)phh, R_ROWS, 256, 256);
    // BN partial stats over h, then finalize
    k_stats<<<STATS_CTAS, 256>>>();
    k_finstats<<<1, 256>>>(bng, bnb);
    // hn (half) = LN(BN(h))
    k_bnln<<<R_ROWS / 8, 256>>>(lng, lnb);
    // mid (half) = relu(hn @ mlp_w1^T + mb1)
    k_mma<true, true><<<dim3(2, MTILES), 256, SMEM_DYN>>>(
        (const __half*)phn, (const __half*)pW1, mb1, (void*)pm, R_ROWS, 512, 256);
    // out (fp32) = mid @ mlp_w2^T + mb2
    k_mma<false, false><<<dim3(1, MTILES), 256, SMEM_DYN>>>(
        (const __half*)pm, (const __half*)pW2, mb2, (void*)out, R_ROWS, 256, 512);
}

// round 11
// speedup vs baseline: 1.2842x; 1.0316x over previous
#include <cuda_runtime.h>
#include <cuda_fp16.h>
#include <cstdint>

#define R_ROWS 264384                    // B*L*J = 64*243*17
#define NCOPY  64                        // striped BN accumulator copies
#define MTILES ((R_ROWS + 127) / 128)    // 2066

// ---------------- scratch (device globals: no allocations allowed) ----------
__device__ __half g_xm[(long long)R_ROWS * 256];    // adj-mixed x (half)
__device__ __half g_hh[(long long)R_ROWS * 256];    // h = relu(xm@Wc+bc) (half)
__device__ __half g_hn[(long long)R_ROWS * 256];    // LN output (half)
__device__ __half g_midh[(long long)R_ROWS * 512];  // MLP hidden (half)
__device__ __half g_Wch[256 * 256];                 // h(w1+w2)   [o][d] K-major
__device__ __half g_W1h[512 * 256];                 // h(mlp_w1)  [h][o] K-major
__device__ __half g_W2h[256 * 512];                 // h(mlp_w2)  [o][h] K-major
__device__ float  g_bc[256];                        // b1+b2
__device__ float  g_stats[NCOPY * 512];             // [sum|sumsq] per copy
__device__ float  g_sc[256];                        // BN scale
__device__ float  g_tsh[256];                       // BN shift

// ---------------- helpers ----------------------------------------------------
__device__ __forceinline__ uint32_t smem_u32(const void* p) {
    uint32_t a;
    asm("{ .reg .u64 t; cvta.to.shared.u64 t, %1; cvt.u32.u64 %0, t; }"
        : "=r"(a) : "l"(p));
    return a;
}
__device__ __forceinline__ void mma_f16(float* d, const uint32_t* a, const uint32_t* b) {
    asm volatile(
        "mma.sync.aligned.m16n8k16.row.col.f32.f16.f16.f32 "
        "{%0,%1,%2,%3}, {%4,%5,%6,%7}, {%8,%9}, {%0,%1,%2,%3};\n"
        : "+f"(d[0]), "+f"(d[1]), "+f"(d[2]), "+f"(d[3])
        : "r"(a[0]), "r"(a[1]), "r"(a[2]), "r"(a[3]), "r"(b[0]), "r"(b[1]));
}
__device__ __forceinline__ void ldsm_x4(uint32_t* r, uint32_t addr) {
    asm volatile("ldmatrix.sync.aligned.m8n8.x4.shared.b16 {%0,%1,%2,%3}, [%4];"
                 : "=r"(r[0]), "=r"(r[1]), "=r"(r[2]), "=r"(r[3]) : "r"(addr));
}
__device__ __forceinline__ void cp16(uint32_t dst, const void* src) {
    asm volatile("cp.async.cg.shared.global [%0], [%1], 16;" :: "r"(dst), "l"(src));
}
__device__ __forceinline__ void cp16z(uint32_t dst, const void* src, unsigned pred16) {
    asm volatile("cp.async.cg.shared.global [%0], [%1], 16, %2;"
                 :: "r"(dst), "l"(src), "r"(pred16));
}

// ---------------- K0: weight prep (half) + stats zeroing ---------------------
__global__ __launch_bounds__(256) void k_prep(
        const float* __restrict__ w1, const float* __restrict__ b1,
        const float* __restrict__ w2, const float* __restrict__ b2,
        const float* __restrict__ mw1, const float* __restrict__ mw2) {
    int i = blockIdx.x * 256 + threadIdx.x;   // 0..131071
    g_W1h[i] = __float2half_rn(mw1[i]);       // native [512,256] K-major
    g_W2h[i] = __float2half_rn(mw2[i]);       // native [256,512] K-major
    if (i < 256 * 256) g_Wch[i] = __float2half_rn(w1[i] + w2[i]);
    if (i < NCOPY * 512) g_stats[i] = 0.f;
    if (i < 256) g_bc[i] = b1[i] + b2[i];
}

// ---------------- K1: per-frame adjacency mix on x, fp32 -> half -------------
__global__ __launch_bounds__(256) void k_xmix(const float* __restrict__ x,
                                              const float* __restrict__ adj) {
    __shared__ float sadj[17 * 17];
    int f = blockIdx.x;
    int o = threadIdx.x;
    for (int i = o; i < 289; i += 256) sadj[i] = adj[i];
    __syncthreads();
    const float* xp = x + (size_t)f * 17 * 256 + o;
    float v[17];
#pragma unroll
    for (int j = 0; j < 17; j++) v[j] = xp[(size_t)j * 256];
    __half* op = g_xm + (size_t)f * 17 * 256 + o;
#pragma unroll
    for (int i = 0; i < 17; i++) {
        float g = 0.f;
#pragma unroll
        for (int j = 0; j < 17; j++) g = fmaf(sadj[i * 17 + j], v[j], g);
        op[(size_t)i * 256] = __float2half_rn(g);
    }
}

// ---------- fp16 mma GEMM: C[M,N] = A[M,K] @ Bw[N,K]^T + bias ----------------
// CTA 128x256, BK=32 (2 k16-steps), 256 thr (8 warps: 2M x 4N), warp 64x64.
// 4-stage cp.async pipeline; LDSM (ldmatrix.x4) fragment loads.
#define LDH   40
#define ASTG  (128 * LDH * 2)             // 10240 B
#define BSTG  (256 * LDH * 2)             // 20480 B
#define STG   (ASTG + BSTG)               // 30720 B
#define SMEM_DYN (4 * STG)                // 122880 B

template <bool RELU, bool OUT_HALF>
__global__ __launch_bounds__(256, 1) void k_mma(
        const __half* __restrict__ A, const __half* __restrict__ Bw,
        const float* __restrict__ bias, void* __restrict__ Cv,
        int M, int N, int K) {
    extern __shared__ char dsm[];
    __shared__ float s_bias[256];

    const int tid = threadIdx.x;
    const int wid = tid >> 5, lane = tid & 31;
    const int wm = wid >> 2, wn = wid & 3;      // warp grid 2x4
    const int row0 = blockIdx.y * 128;
    const int n0 = blockIdx.x * 256;
    const int NC = K >> 5;

    const uint32_t sb = smem_u32(dsm);

    s_bias[tid] = bias[n0 + tid];

    // chunk loader: A 128 rows x 32 halves (4 x 16B segs), B 256 rows x 4 segs
    auto load_chunk = [&](int ck, int st) {
        const int k0 = ck << 5;
        const uint32_t sA = sb + (uint32_t)st * STG;
        const uint32_t sB = sA + ASTG;
#pragma unroll
        for (int j = 0; j < 2; j++) {           // 512 segs
            int id = tid + (j << 8);
            int r = id >> 2, seg = id & 3;
            int gr = row0 + r;
            const __half* gp =
                A + (size_t)(gr < M ? gr : (M - 1)) * K + k0 + (seg << 3);
            cp16z(sA + (uint32_t)(r * LDH + (seg << 3)) * 2u, gp,
                  gr < M ? 16u : 0u);
        }
#pragma unroll
        for (int j = 0; j < 4; j++) {           // 1024 segs
            int id = tid + (j << 8);
            int r = id >> 2, seg = id & 3;
            const __half* gp = Bw + (size_t)(n0 + r) * K + k0 + (seg << 3);
            cp16(sB + (uint32_t)(r * LDH + (seg << 3)) * 2u, gp);
        }
        asm volatile("cp.async.commit_group;" ::: "memory");
    };

    float acc[4][8][4];
#pragma unroll
    for (int i = 0; i < 4; i++)
#pragma unroll
        for (int j = 0; j < 8; j++)
#pragma unroll
            for (int r = 0; r < 4; r++) acc[i][j][r] = 0.f;

    load_chunk(0, 0);
    load_chunk(1, 1);
    load_chunk(2, 2);

    // LDSM lane base offsets (bytes, within a stage)
    //  A x4: lanes 0-15 -> rows (lane&15) at k0; lanes 16-31 -> same rows k0+8
    const uint32_t aOff =
        ((uint32_t)(wm * 64 + (lane & 15)) * LDH + (uint32_t)((lane >> 4) << 3)) * 2u;
    //  B x4 (group g covers nt=2g,2g+1): matrix (lane>>3): nt_off=(mi>>1)*8, kb=mi&1
    const uint32_t bOff =
        ((uint32_t)(wn * 64 + (((lane >> 3) >> 1) << 3) + (lane & 7)) * LDH
         + (uint32_t)(((lane >> 3) & 1) << 3)) * 2u;

    for (int c = 0; c < NC; c++) {
        if (c + 2 < NC)
            asm volatile("cp.async.wait_group 2;" ::: "memory");
        else if (c + 1 < NC)
            asm volatile("cp.async.wait_group 1;" ::: "memory");
        else
            asm volatile("cp.async.wait_group 0;" ::: "memory");
        __syncthreads();   // chunk c visible; all warps done reading c-1

        const int st = c & 3;
        const uint32_t aBase = sb + st * STG + aOff;
        const uint32_t bBase = sb + st * STG + ASTG + bOff;
#pragma unroll
        for (int s = 0; s < 2; s++) {           // 2 k-steps of 16
            const uint32_t ks = s * 32u;        // 16 halves
            uint32_t af[4][4], bf[4][4];        // bf[g] = {nt2g:k0,k8, nt2g+1:k0,k8}
#pragma unroll
            for (int mt = 0; mt < 4; mt++)
                ldsm_x4(af[mt], aBase + ks + (uint32_t)(mt * 16 * LDH) * 2u);
#pragma unroll
            for (int g = 0; g < 4; g++)
                ldsm_x4(bf[g], bBase + ks + (uint32_t)(g * 16 * LDH) * 2u);
#pragma unroll
            for (int mt = 0; mt < 4; mt++)
#pragma unroll
                for (int g = 0; g < 4; g++) {
                    mma_f16(acc[mt][2 * g], af[mt], &bf[g][0]);
                    mma_f16(acc[mt][2 * g + 1], af[mt], &bf[g][2]);
                }
        }
        // prefetch chunk c+3 into the freed stage ((c+3)&3 == (c-1)&3)
        if (c + 3 < NC) load_chunk(c + 3, (c + 3) & 3);
    }

    // epilogue: bias (+relu), fp32 or half stores
    const int qr = lane >> 2, qc = lane & 3;
#pragma unroll
    for (int mt = 0; mt < 4; mt++) {
        int r0 = row0 + wm * 64 + mt * 16 + qr;
#pragma unroll
        for (int nt = 0; nt < 8; nt++) {
            int cc = wn * 64 + nt * 8 + qc * 2;
            float b0 = s_bias[cc], b1 = s_bias[cc + 1];
            float v0 = acc[mt][nt][0] + b0, v1 = acc[mt][nt][1] + b1;
            float v2 = acc[mt][nt][2] + b0, v3 = acc[mt][nt][3] + b1;
            if (RELU) {
                v0 = fmaxf(v0, 0.f); v1 = fmaxf(v1, 0.f);
                v2 = fmaxf(v2, 0.f); v3 = fmaxf(v3, 0.f);
            }
            if (OUT_HALF) {
                __half* C = (__half*)Cv;
                if (r0 < M)
                    *(__half2*)(C + (size_t)r0 * N + n0 + cc) = __floats2half2_rn(v0, v1);
                if (r0 + 8 < M)
                    *(__half2*)(C + (size_t)(r0 + 8) * N + n0 + cc) = __floats2half2_rn(v2, v3);
            } else {
                float* C = (float*)Cv;
                if (r0 < M)
                    *(float2*)(C + (size_t)r0 * N + n0 + cc) = make_float2(v0, v1);
                if (r0 + 8 < M)
                    *(float2*)(C + (size_t)(r0 + 8) * N + n0 + cc) = make_float2(v2, v3);
            }
        }
    }
}

// ---------------- K2b: BN partial stats over g_hh (half) ---------------------
#define STATS_CTAS 1024
__global__ __launch_bounds__(256) void k_stats() {
    int tid = threadIdx.x;
    int ch2 = tid & 127;                    // half2 channel index
    int rg = tid >> 7;                      // row group (0/1)
    const __half2* hp = (const __half2*)g_hh;
    float s0 = 0.f, s1 = 0.f, q0 = 0.f, q1 = 0.f;
    for (long long r = (long long)blockIdx.x * 2 + rg; r < R_ROWS;
         r += (long long)STATS_CTAS * 2) {
        float2 v = __half22float2(hp[r * 128 + ch2]);
        s0 += v.x; s1 += v.y;
        q0 = fmaf(v.x, v.x, q0);
        q1 = fmaf(v.y, v.y, q1);
    }
    float* st = g_stats + (size_t)(blockIdx.x & (NCOPY - 1)) * 512;
    atomicAdd(st + 2 * ch2, s0);
    atomicAdd(st + 2 * ch2 + 1, s1);
    atomicAdd(st + 256 + 2 * ch2, q0);
    atomicAdd(st + 256 + 2 * ch2 + 1, q1);
}

// ---------------- K3: finalize BN statistics ---------------------------------
__global__ __launch_bounds__(256) void k_finstats(const float* __restrict__ bg,
                                                  const float* __restrict__ bb) {
    int o = threadIdx.x;
    float s = 0.f, s2 = 0.f;
#pragma unroll 8
    for (int c = 0; c < NCOPY; c++) {
        s += g_stats[c * 512 + o];
        s2 += g_stats[c * 512 + 256 + o];
    }
    const float inv = 1.f / (float)R_ROWS;
    float mu = s * inv;
    float var = fmaxf(s2 * inv - mu * mu, 0.f);
    float rs = rsqrtf(var + 1e-5f);
    float sc = rs * bg[o];
    g_sc[o] = sc;
    g_tsh[o] = bb[o] - mu * sc;
}

// ---------------- K4: BN apply + LayerNorm (h half -> hn half) ---------------
__global__ __launch_bounds__(256) void k_bnln(const float* __restrict__ lg,
                                              const float* __restrict__ lb) {
    int row = blockIdx.x * 8 + (threadIdx.x >> 5);
    int lane = threadIdx.x & 31;
    const __half2* hp = (const __half2*)(g_hh + (size_t)row * 256);
    float v[8];
    float s = 0.f, s2 = 0.f;
#pragma unroll
    for (int i = 0; i < 4; i++) {
        int k2 = lane + 32 * i;                 // half2 index (0..127)
        float2 xv = __half22float2(hp[k2]);
        float x0 = fmaf(xv.x, g_sc[2 * k2], g_tsh[2 * k2]);
        float x1 = fmaf(xv.y, g_sc[2 * k2 + 1], g_tsh[2 * k2 + 1]);
        v[2 * i] = x0; v[2 * i + 1] = x1;
        s += x0 + x1;
        s2 = fmaf(x0, x0, s2);
        s2 = fmaf(x1, x1, s2);
    }
#pragma unroll
    for (int off = 16; off; off >>= 1) {
        s += __shfl_xor_sync(0xffffffffu, s, off);
        s2 += __shfl_xor_sync(0xffffffffu, s2, off);
    }
    float mu = s * (1.f / 256.f);
    float var = fmaxf(s2 * (1.f / 256.f) - mu * mu, 0.f);
    float rs = rsqrtf(var + 1e-5f);
    __half2* op = (__half2*)(g_hn + (size_t)row * 256);
#pragma unroll
    for (int i = 0; i < 4; i++) {
        int k2 = lane + 32 * i;
        float y0 = fmaf((v[2 * i] - mu) * rs, lg[2 * k2], lb[2 * k2]);
        float y1 = fmaf((v[2 * i + 1] - mu) * rs, lg[2 * k2 + 1], lb[2 * k2 + 1]);
        op[k2] = __floats2half2_rn(y0, y1);
    }
}

// ---------------- host side --------------------------------------------------
extern "C" void kernel_launch(void* const* d_in, const int* in_sizes, int n_in,
                              void* d_out, int out_size) {
    (void)in_sizes; (void)n_in; (void)out_size;
    const float* x   = (const float*)d_in[0];
    const float* adj = (const float*)d_in[1];
    const float* w1  = (const float*)d_in[2];
    const float* b1  = (const float*)d_in[3];
    const float* w2  = (const float*)d_in[4];
    const float* b2  = (const float*)d_in[5];
    const float* bng = (const float*)d_in[6];
    const float* bnb = (const float*)d_in[7];
    const float* lng = (const float*)d_in[8];
    const float* lnb = (const float*)d_in[9];
    const float* mw1 = (const float*)d_in[10];
    const float* mb1 = (const float*)d_in[11];
    const float* mw2 = (const float*)d_in[12];
    const float* mb2 = (const float*)d_in[13];
    float* out = (float*)d_out;

    void *pxm = 0, *phh = 0, *phn = 0, *pm = 0, *pWc = 0, *pW1 = 0, *pW2 = 0, *pbc = 0;
    cudaGetSymbolAddress(&pxm, g_xm);
    cudaGetSymbolAddress(&phh, g_hh);
    cudaGetSymbolAddress(&phn, g_hn);
    cudaGetSymbolAddress(&pm, g_midh);
    cudaGetSymbolAddress(&pWc, g_Wch);
    cudaGetSymbolAddress(&pW1, g_W1h);
    cudaGetSymbolAddress(&pW2, g_W2h);
    cudaGetSymbolAddress(&pbc, g_bc);

    cudaFuncSetAttribute(k_mma<true, true>,
                         cudaFuncAttributeMaxDynamicSharedMemorySize, SMEM_DYN);
    cudaFuncSetAttribute(k_mma<false, false>,
                         cudaFuncAttributeMaxDynamicSharedMemorySize, SMEM_DYN);

    k_prep<<<512, 256>>>(w1, b1, w2, b2, mw1, mw2);
    // xm = adj @ x (per frame), half
    k_xmix<<<R_ROWS / 17, 256>>>(x, adj);
    // h (half) = relu(xm @ Wc^T + bc)
    k_mma<true, true><<<dim3(1, MTILES), 256, SMEM_DYN>>>(
        (const __half*)pxm, (const __half*)pWc, (const float*)pbc,
        (void*)phh, R_ROWS, 256, 256);
    // BN partial stats over h, then finalize
    k_stats<<<STATS_CTAS, 256>>>();
    k_finstats<<<1, 256>>>(bng, bnb);
    // hn (half) = LN(BN(h))
    k_bnln<<<R_ROWS / 8, 256>>>(lng, lnb);
    // mid (half) = relu(hn @ mlp_w1^T + mb1)
    k_mma<true, true><<<dim3(2, MTILES), 256, SMEM_DYN>>>(
        (const __half*)phn, (const __half*)pW1, mb1, (void*)pm, R_ROWS, 512, 256);
    // out (fp32) = mid @ mlp_w2^T + mb2
    k_mma<false, false><<<dim3(1, MTILES), 256, SMEM_DYN>>>(
        (const __half*)pm, (const __half*)pW2, mb2, (void*)out, R_ROWS, 256, 512);
}

// round 12
// speedup vs baseline: 1.3791x; 1.0739x over previous
#include <cuda_runtime.h>
#include <cuda_fp16.h>
#include <cstdint>

#define R_ROWS 264384                    // B*L*J = 64*243*17
#define NCOPY  64                        // striped BN accumulator copies
#define MTILES ((R_ROWS + 127) / 128)    // 2066

// ---------------- scratch (device globals: no allocations allowed) ----------
__device__ __half g_xm[(long long)R_ROWS * 256];    // adj-mixed x (half)
__device__ __half g_hh[(long long)R_ROWS * 256];    // h = relu(xm@Wc+bc) (half)
__device__ __half g_hn[(long long)R_ROWS * 256];    // LN output (half)
__device__ __half g_midh[(long long)R_ROWS * 512];  // MLP hidden (half)
__device__ __half g_Wch[256 * 256];                 // h(w1+w2)   [o][d] K-major
__device__ __half g_W1h[512 * 256];                 // h(mlp_w1)  [h][o] K-major
__device__ __half g_W2h[256 * 512];                 // h(mlp_w2)  [o][h] K-major
__device__ float  g_bc[256];                        // b1+b2
__device__ float  g_stats[NCOPY * 512];             // [sum|sumsq] per copy
__device__ float  g_sc[256];                        // BN scale
__device__ float  g_tsh[256];                       // BN shift

// ---------------- helpers ----------------------------------------------------
__device__ __forceinline__ uint32_t smem_u32(const void* p) {
    uint32_t a;
    asm("{ .reg .u64 t; cvta.to.shared.u64 t, %1; cvt.u32.u64 %0, t; }"
        : "=r"(a) : "l"(p));
    return a;
}
__device__ __forceinline__ void mma_f16(float* d, const uint32_t* a, const uint32_t* b) {
    asm volatile(
        "mma.sync.aligned.m16n8k16.row.col.f32.f16.f16.f32 "
        "{%0,%1,%2,%3}, {%4,%5,%6,%7}, {%8,%9}, {%0,%1,%2,%3};\n"
        : "+f"(d[0]), "+f"(d[1]), "+f"(d[2]), "+f"(d[3])
        : "r"(a[0]), "r"(a[1]), "r"(a[2]), "r"(a[3]), "r"(b[0]), "r"(b[1]));
}
__device__ __forceinline__ void ldsm_x4(uint32_t* r, uint32_t addr) {
    asm volatile("ldmatrix.sync.aligned.m8n8.x4.shared.b16 {%0,%1,%2,%3}, [%4];"
                 : "=r"(r[0]), "=r"(r[1]), "=r"(r[2]), "=r"(r[3]) : "r"(addr));
}
__device__ __forceinline__ void cp16(uint32_t dst, const void* src) {
    asm volatile("cp.async.cg.shared.global [%0], [%1], 16;" :: "r"(dst), "l"(src));
}
__device__ __forceinline__ void cp16z(uint32_t dst, const void* src, unsigned pred16) {
    asm volatile("cp.async.cg.shared.global [%0], [%1], 16, %2;"
                 :: "r"(dst), "l"(src), "r"(pred16));
}

// ---------------- K0: weight prep (half) + stats zeroing ---------------------
__global__ __launch_bounds__(256) void k_prep(
        const float* __restrict__ w1, const float* __restrict__ b1,
        const float* __restrict__ w2, const float* __restrict__ b2,
        const float* __restrict__ mw1, const float* __restrict__ mw2) {
    int i = blockIdx.x * 256 + threadIdx.x;   // 0..131071
    g_W1h[i] = __float2half_rn(mw1[i]);       // native [512,256] K-major
    g_W2h[i] = __float2half_rn(mw2[i]);       // native [256,512] K-major
    if (i < 256 * 256) g_Wch[i] = __float2half_rn(w1[i] + w2[i]);
    if (i < NCOPY * 512) g_stats[i] = 0.f;
    if (i < 256) g_bc[i] = b1[i] + b2[i];
}

// ---------------- K1: per-frame adjacency mix on x, fp32 -> half -------------
__global__ __launch_bounds__(256) void k_xmix(const float* __restrict__ x,
                                              const float* __restrict__ adj) {
    __shared__ float sadj[17 * 17];
    int f = blockIdx.x;
    int o = threadIdx.x;
    for (int i = o; i < 289; i += 256) sadj[i] = adj[i];
    __syncthreads();
    const float* xp = x + (size_t)f * 17 * 256 + o;
    float v[17];
#pragma unroll
    for (int j = 0; j < 17; j++) v[j] = xp[(size_t)j * 256];
    __half* op = g_xm + (size_t)f * 17 * 256 + o;
#pragma unroll
    for (int i = 0; i < 17; i++) {
        float g = 0.f;
#pragma unroll
        for (int j = 0; j < 17; j++) g = fmaf(sadj[i * 17 + j], v[j], g);
        op[(size_t)i * 256] = __float2half_rn(g);
    }
}

// ---------- fp16 mma GEMM: C[M,N] = A[M,K] @ Bw[N,K]^T + bias ----------------
// CTA 128x256, BK=64 (4 k16-steps), 256 thr (8 warps: 2M x 4N), warp 64x64.
// 3-stage cp.async pipeline; LDSM fragment loads double-buffered across k-steps.
#define LDH   72                          // 64 halves + 8 pad
#define ASTG  (128 * LDH * 2)             // 18432 B
#define BSTG  (256 * LDH * 2)             // 36864 B
#define STG   (ASTG + BSTG)               // 55296 B
#define SMEM_DYN (3 * STG)                // 165888 B

template <bool RELU, bool OUT_HALF>
__global__ __launch_bounds__(256, 1) void k_mma(
        const __half* __restrict__ A, const __half* __restrict__ Bw,
        const float* __restrict__ bias, void* __restrict__ Cv,
        int M, int N, int K) {
    extern __shared__ char dsm[];
    __shared__ float s_bias[256];

    const int tid = threadIdx.x;
    const int wid = tid >> 5, lane = tid & 31;
    const int wm = wid >> 2, wn = wid & 3;      // warp grid 2x4
    const int row0 = blockIdx.y * 128;
    const int n0 = blockIdx.x * 256;
    const int NC = K >> 6;                      // 64-wide chunks

    const uint32_t sb = smem_u32(dsm);

    s_bias[tid] = bias[n0 + tid];

    // chunk loader: A 128 rows x 64 halves (8 x 16B segs), B 256 rows x 8 segs
    auto load_chunk = [&](int ck, int st) {
        const int k0 = ck << 6;
        const uint32_t sA = sb + (uint32_t)st * STG;
        const uint32_t sB = sA + ASTG;
#pragma unroll
        for (int j = 0; j < 4; j++) {           // 1024 segs
            int id = tid + (j << 8);
            int r = id >> 3, seg = id & 7;
            int gr = row0 + r;
            const __half* gp =
                A + (size_t)(gr < M ? gr : (M - 1)) * K + k0 + (seg << 3);
            cp16z(sA + (uint32_t)(r * LDH + (seg << 3)) * 2u, gp,
                  gr < M ? 16u : 0u);
        }
#pragma unroll
        for (int j = 0; j < 8; j++) {           // 2048 segs
            int id = tid + (j << 8);
            int r = id >> 3, seg = id & 7;
            const __half* gp = Bw + (size_t)(n0 + r) * K + k0 + (seg << 3);
            cp16(sB + (uint32_t)(r * LDH + (seg << 3)) * 2u, gp);
        }
        asm volatile("cp.async.commit_group;" ::: "memory");
    };

    float acc[4][8][4];
#pragma unroll
    for (int i = 0; i < 4; i++)
#pragma unroll
        for (int j = 0; j < 8; j++)
#pragma unroll
            for (int r = 0; r < 4; r++) acc[i][j][r] = 0.f;

    load_chunk(0, 0);
    if (NC > 1) load_chunk(1, 1);

    // LDSM lane base offsets (bytes, within a stage)
    const uint32_t aOff =
        ((uint32_t)(wm * 64 + (lane & 15)) * LDH + (uint32_t)((lane >> 4) << 3)) * 2u;
    const uint32_t bOff =
        ((uint32_t)(wn * 64 + (((lane >> 3) >> 1) << 3) + (lane & 7)) * LDH
         + (uint32_t)(((lane >> 3) & 1) << 3)) * 2u;

    uint32_t af[2][4][4], bf[2][4][4];
    for (int c = 0; c < NC; c++) {
        if (c + 1 < NC)
            asm volatile("cp.async.wait_group 1;" ::: "memory");
        else
            asm volatile("cp.async.wait_group 0;" ::: "memory");
        __syncthreads();   // chunk c visible; all warps done reading c-1

        const int st = c % 3;
        const uint32_t aBase = sb + st * STG + aOff;
        const uint32_t bBase = sb + st * STG + ASTG + bOff;

        // prime k-step 0 fragments
#pragma unroll
        for (int mt = 0; mt < 4; mt++)
            ldsm_x4(af[0][mt], aBase + (uint32_t)(mt * 16 * LDH) * 2u);
#pragma unroll
        for (int g = 0; g < 4; g++)
            ldsm_x4(bf[0][g], bBase + (uint32_t)(g * 16 * LDH) * 2u);

#pragma unroll
        for (int s = 0; s < 4; s++) {           // 4 k-steps of 16
            const int cur = s & 1, nxt = cur ^ 1;
            if (s < 3) {                        // prefetch fragments for s+1
                const uint32_t ks = (uint32_t)(s + 1) * 32u;
#pragma unroll
                for (int mt = 0; mt < 4; mt++)
                    ldsm_x4(af[nxt][mt], aBase + ks + (uint32_t)(mt * 16 * LDH) * 2u);
#pragma unroll
                for (int g = 0; g < 4; g++)
                    ldsm_x4(bf[nxt][g], bBase + ks + (uint32_t)(g * 16 * LDH) * 2u);
            }
#pragma unroll
            for (int mt = 0; mt < 4; mt++)
#pragma unroll
                for (int g = 0; g < 4; g++) {
                    mma_f16(acc[mt][2 * g], af[cur][mt], &bf[cur][g][0]);
                    mma_f16(acc[mt][2 * g + 1], af[cur][mt], &bf[cur][g][2]);
                }
        }
        // prefetch chunk c+2 into the stage just freed
        if (c + 2 < NC) load_chunk(c + 2, (c + 2) % 3);
    }

    // epilogue: bias (+relu), fp32 or half stores
    const int qr = lane >> 2, qc = lane & 3;
#pragma unroll
    for (int mt = 0; mt < 4; mt++) {
        int r0 = row0 + wm * 64 + mt * 16 + qr;
#pragma unroll
        for (int nt = 0; nt < 8; nt++) {
            int cc = wn * 64 + nt * 8 + qc * 2;
            float b0 = s_bias[cc], b1 = s_bias[cc + 1];
            float v0 = acc[mt][nt][0] + b0, v1 = acc[mt][nt][1] + b1;
            float v2 = acc[mt][nt][2] + b0, v3 = acc[mt][nt][3] + b1;
            if (RELU) {
                v0 = fmaxf(v0, 0.f); v1 = fmaxf(v1, 0.f);
                v2 = fmaxf(v2, 0.f); v3 = fmaxf(v3, 0.f);
            }
            if (OUT_HALF) {
                __half* C = (__half*)Cv;
                if (r0 < M)
                    *(__half2*)(C + (size_t)r0 * N + n0 + cc) = __floats2half2_rn(v0, v1);
                if (r0 + 8 < M)
                    *(__half2*)(C + (size_t)(r0 + 8) * N + n0 + cc) = __floats2half2_rn(v2, v3);
            } else {
                float* C = (float*)Cv;
                if (r0 < M)
                    *(float2*)(C + (size_t)r0 * N + n0 + cc) = make_float2(v0, v1);
                if (r0 + 8 < M)
                    *(float2*)(C + (size_t)(r0 + 8) * N + n0 + cc) = make_float2(v2, v3);
            }
        }
    }
}

// ---------------- K2b: BN partial stats over g_hh (half) ---------------------
#define STATS_CTAS 1024
__global__ __launch_bounds__(256) void k_stats() {
    int tid = threadIdx.x;
    int ch2 = tid & 127;                    // half2 channel index
    int rg = tid >> 7;                      // row group (0/1)
    const __half2* hp = (const __half2*)g_hh;
    float s0 = 0.f, s1 = 0.f, q0 = 0.f, q1 = 0.f;
    for (long long r = (long long)blockIdx.x * 2 + rg; r < R_ROWS;
         r += (long long)STATS_CTAS * 2) {
        float2 v = __half22float2(hp[r * 128 + ch2]);
        s0 += v.x; s1 += v.y;
        q0 = fmaf(v.x, v.x, q0);
        q1 = fmaf(v.y, v.y, q1);
    }
    float* st = g_stats + (size_t)(blockIdx.x & (NCOPY - 1)) * 512;
    atomicAdd(st + 2 * ch2, s0);
    atomicAdd(st + 2 * ch2 + 1, s1);
    atomicAdd(st + 256 + 2 * ch2, q0);
    atomicAdd(st + 256 + 2 * ch2 + 1, q1);
}

// ---------------- K3: finalize BN statistics ---------------------------------
__global__ __launch_bounds__(256) void k_finstats(const float* __restrict__ bg,
                                                  const float* __restrict__ bb) {
    int o = threadIdx.x;
    float s = 0.f, s2 = 0.f;
#pragma unroll 8
    for (int c = 0; c < NCOPY; c++) {
        s += g_stats[c * 512 + o];
        s2 += g_stats[c * 512 + 256 + o];
    }
    const float inv = 1.f / (float)R_ROWS;
    float mu = s * inv;
    float var = fmaxf(s2 * inv - mu * mu, 0.f);
    float rs = rsqrtf(var + 1e-5f);
    float sc = rs * bg[o];
    g_sc[o] = sc;
    g_tsh[o] = bb[o] - mu * sc;
}

// ---------------- K4: BN apply + LayerNorm (h half -> hn half) ---------------
__global__ __launch_bounds__(256) void k_bnln(const float* __restrict__ lg,
                                              const float* __restrict__ lb) {
    int row = blockIdx.x * 8 + (threadIdx.x >> 5);
    int lane = threadIdx.x & 31;
    const __half2* hp = (const __half2*)(g_hh + (size_t)row * 256);
    float v[8];
    float s = 0.f, s2 = 0.f;
#pragma unroll
    for (int i = 0; i < 4; i++) {
        int k2 = lane + 32 * i;                 // half2 index (0..127)
        float2 xv = __half22float2(hp[k2]);
        float x0 = fmaf(xv.x, g_sc[2 * k2], g_tsh[2 * k2]);
        float x1 = fmaf(xv.y, g_sc[2 * k2 + 1], g_tsh[2 * k2 + 1]);
        v[2 * i] = x0; v[2 * i + 1] = x1;
        s += x0 + x1;
        s2 = fmaf(x0, x0, s2);
        s2 = fmaf(x1, x1, s2);
    }
#pragma unroll
    for (int off = 16; off; off >>= 1) {
        s += __shfl_xor_sync(0xffffffffu, s, off);
        s2 += __shfl_xor_sync(0xffffffffu, s2, off);
    }
    float mu = s * (1.f / 256.f);
    float var = fmaxf(s2 * (1.f / 256.f) - mu * mu, 0.f);
    float rs = rsqrtf(var + 1e-5f);
    __half2* op = (__half2*)(g_hn + (size_t)row * 256);
#pragma unroll
    for (int i = 0; i < 4; i++) {
        int k2 = lane + 32 * i;
        float y0 = fmaf((v[2 * i] - mu) * rs, lg[2 * k2], lb[2 * k2]);
        float y1 = fmaf((v[2 * i + 1] - mu) * rs, lg[2 * k2 + 1], lb[2 * k2 + 1]);
        op[k2] = __floats2half2_rn(y0, y1);
    }
}

// ---------------- host side --------------------------------------------------
extern "C" void kernel_launch(void* const* d_in, const int* in_sizes, int n_in,
                              void* d_out, int out_size) {
    (void)in_sizes; (void)n_in; (void)out_size;
    const float* x   = (const float*)d_in[0];
    const float* adj = (const float*)d_in[1];
    const float* w1  = (const float*)d_in[2];
    const float* b1  = (const float*)d_in[3];
    const float* w2  = (const float*)d_in[4];
    const float* b2  = (const float*)d_in[5];
    const float* bng = (const float*)d_in[6];
    const float* bnb = (const float*)d_in[7];
    const float* lng = (const float*)d_in[8];
    const float* lnb = (const float*)d_in[9];
    const float* mw1 = (const float*)d_in[10];
    const float* mb1 = (const float*)d_in[11];
    const float* mw2 = (const float*)d_in[12];
    const float* mb2 = (const float*)d_in[13];
    float* out = (float*)d_out;

    void *pxm = 0, *phh = 0, *phn = 0, *pm = 0, *pWc = 0, *pW1 = 0, *pW2 = 0, *pbc = 0;
    cudaGetSymbolAddress(&pxm, g_xm);
    cudaGetSymbolAddress(&phh, g_hh);
    cudaGetSymbolAddress(&phn, g_hn);
    cudaGetSymbolAddress(&pm, g_midh);
    cudaGetSymbolAddress(&pWc, g_Wch);
    cudaGetSymbolAddress(&pW1, g_W1h);
    cudaGetSymbolAddress(&pW2, g_W2h);
    cudaGetSymbolAddress(&pbc, g_bc);

    cudaFuncSetAttribute(k_mma<true, true>,
                         cudaFuncAttributeMaxDynamicSharedMemorySize, SMEM_DYN);
    cudaFuncSetAttribute(k_mma<false, false>,
                         cudaFuncAttributeMaxDynamicSharedMemorySize, SMEM_DYN);

    k_prep<<<512, 256>>>(w1, b1, w2, b2, mw1, mw2);
    // xm = adj @ x (per frame), half
    k_xmix<<<R_ROWS / 17, 256>>>(x, adj);
    // h (half) = relu(xm @ Wc^T + bc)
    k_mma<true, true><<<dim3(1, MTILES), 256, SMEM_DYN>>>(
        (const __half*)pxm, (const __half*)pWc, (const float*)pbc,
        (void*)phh, R_ROWS, 256, 256);
    // BN partial stats over h, then finalize
    k_stats<<<STATS_CTAS, 256>>>();
    k_finstats<<<1, 256>>>(bng, bnb);
    // hn (half) = LN(BN(h))
    k_bnln<<<R_ROWS / 8, 256>>>(lng, lnb);
    // mid (half) = relu(hn @ mlp_w1^T + mb1)
    k_mma<true, true><<<dim3(2, MTILES), 256, SMEM_DYN>>>(
        (const __half*)phn, (const __half*)pW1, mb1, (void*)pm, R_ROWS, 512, 256);
    // out (fp32) = mid @ mlp_w2^T + mb2
    k_mma<false, false><<<dim3(1, MTILES), 256, SMEM_DYN>>>(
        (const __half*)pm, (const __half*)pW2, mb2, (void*)out, R_ROWS, 256, 512);
}

// round 13
// speedup vs baseline: 1.4133x; 1.0248x over previous
#include <cuda_runtime.h>
#include <cuda_fp16.h>
#include <cstdint>

#define R_ROWS 264384                    // B*L*J = 64*243*17
#define NCOPY  64                        // striped BN accumulator copies
#define MTILES ((R_ROWS + 127) / 128)    // 2066

// ---------------- scratch (device globals: no allocations allowed) ----------
__device__ __half g_xm[(long long)R_ROWS * 256];    // adj-mixed x (half)
__device__ __half g_hh[(long long)R_ROWS * 256];    // h = relu(xm@Wc+bc) (half)
__device__ __half g_hn[(long long)R_ROWS * 256];    // LN output (half)
__device__ __half g_midh[(long long)R_ROWS * 512];  // MLP hidden (half)
__device__ __half g_Wch[256 * 256];                 // h(w1+w2)   [o][d] K-major
__device__ __half g_W1h[512 * 256];                 // h(mlp_w1)  [h][o] K-major
__device__ __half g_W2h[256 * 512];                 // h(mlp_w2)  [o][h] K-major
__device__ float  g_bc[256];                        // b1+b2
__device__ float  g_stats[NCOPY * 512];             // [sum|sumsq] per copy
__device__ float  g_sc[256];                        // BN scale
__device__ float  g_tsh[256];                       // BN shift

// ---------------- helpers ----------------------------------------------------
__device__ __forceinline__ uint32_t smem_u32(const void* p) {
    uint32_t a;
    asm("{ .reg .u64 t; cvta.to.shared.u64 t, %1; cvt.u32.u64 %0, t; }"
        : "=r"(a) : "l"(p));
    return a;
}
__device__ __forceinline__ void mma_f16(float* d, const uint32_t* a, const uint32_t* b) {
    asm volatile(
        "mma.sync.aligned.m16n8k16.row.col.f32.f16.f16.f32 "
        "{%0,%1,%2,%3}, {%4,%5,%6,%7}, {%8,%9}, {%0,%1,%2,%3};\n"
        : "+f"(d[0]), "+f"(d[1]), "+f"(d[2]), "+f"(d[3])
        : "r"(a[0]), "r"(a[1]), "r"(a[2]), "r"(a[3]), "r"(b[0]), "r"(b[1]));
}
__device__ __forceinline__ void ldsm_x4(uint32_t* r, uint32_t addr) {
    asm volatile("ldmatrix.sync.aligned.m8n8.x4.shared.b16 {%0,%1,%2,%3}, [%4];"
                 : "=r"(r[0]), "=r"(r[1]), "=r"(r[2]), "=r"(r[3]) : "r"(addr));
}
__device__ __forceinline__ void cp16(uint32_t dst, const void* src) {
    asm volatile("cp.async.cg.shared.global [%0], [%1], 16;" :: "r"(dst), "l"(src));
}
__device__ __forceinline__ void cp16z(uint32_t dst, const void* src, unsigned pred16) {
    asm volatile("cp.async.cg.shared.global [%0], [%1], 16, %2;"
                 :: "r"(dst), "l"(src), "r"(pred16));
}

// ---------------- K0: weight prep (half) + stats zeroing ---------------------
__global__ __launch_bounds__(256) void k_prep(
        const float* __restrict__ w1, const float* __restrict__ b1,
        const float* __restrict__ w2, const float* __restrict__ b2,
        const float* __restrict__ mw1, const float* __restrict__ mw2) {
    int i = blockIdx.x * 256 + threadIdx.x;   // 0..131071
    g_W1h[i] = __float2half_rn(mw1[i]);       // native [512,256] K-major
    g_W2h[i] = __float2half_rn(mw2[i]);       // native [256,512] K-major
    if (i < 256 * 256) g_Wch[i] = __float2half_rn(w1[i] + w2[i]);
    if (i < NCOPY * 512) g_stats[i] = 0.f;
    if (i < 256) g_bc[i] = b1[i] + b2[i];
}

// ---------------- K1: per-frame adjacency mix on x, fp32 -> half -------------
__global__ __launch_bounds__(256) void k_xmix(const float* __restrict__ x,
                                              const float* __restrict__ adj) {
    __shared__ float sadj[17 * 17];
    int f = blockIdx.x;
    int o = threadIdx.x;
    for (int i = o; i < 289; i += 256) sadj[i] = adj[i];
    __syncthreads();
    const float* xp = x + (size_t)f * 17 * 256 + o;
    float v[17];
#pragma unroll
    for (int j = 0; j < 17; j++) v[j] = xp[(size_t)j * 256];
    __half* op = g_xm + (size_t)f * 17 * 256 + o;
#pragma unroll
    for (int i = 0; i < 17; i++) {
        float g = 0.f;
#pragma unroll
        for (int j = 0; j < 17; j++) g = fmaf(sadj[i * 17 + j], v[j], g);
        op[(size_t)i * 256] = __float2half_rn(g);
    }
}

// ---------- fp16 mma GEMM: C[M,N] = A[M,K] @ Bw[N,K]^T + bias ----------------
// CTA 128x256, BK=64 (4 k16-steps), 256 thr (8 warps: 2M x 4N), warp 64x64.
// 3-stage cp.async pipeline; LDSM fragments double-buffered across k-steps.
// STATS: nt-outer epilogue, shfl-reduced per-channel sums -> striped global atomics.
#define LDH   72                          // 64 halves + 8 pad
#define ASTG  (128 * LDH * 2)             // 18432 B
#define BSTG  (256 * LDH * 2)             // 36864 B
#define STG   (ASTG + BSTG)               // 55296 B
#define SMEM_DYN (3 * STG)                // 165888 B

template <bool RELU, bool OUT_HALF, bool STATS>
__global__ __launch_bounds__(256, 1) void k_mma(
        const __half* __restrict__ A, const __half* __restrict__ Bw,
        const float* __restrict__ bias, void* __restrict__ Cv,
        int M, int N, int K) {
    extern __shared__ char dsm[];
    __shared__ float s_bias[256];

    const int tid = threadIdx.x;
    const int wid = tid >> 5, lane = tid & 31;
    const int wm = wid >> 2, wn = wid & 3;      // warp grid 2x4
    const int row0 = blockIdx.y * 128;
    const int n0 = blockIdx.x * 256;
    const int NC = K >> 6;                      // 64-wide chunks

    const uint32_t sb = smem_u32(dsm);

    s_bias[tid] = bias[n0 + tid];

    // chunk loader: A 128 rows x 64 halves (8 x 16B segs), B 256 rows x 8 segs
    auto load_chunk = [&](int ck, int st) {
        const int k0 = ck << 6;
        const uint32_t sA = sb + (uint32_t)st * STG;
        const uint32_t sB = sA + ASTG;
#pragma unroll
        for (int j = 0; j < 4; j++) {           // 1024 segs
            int id = tid + (j << 8);
            int r = id >> 3, seg = id & 7;
            int gr = row0 + r;
            const __half* gp =
                A + (size_t)(gr < M ? gr : (M - 1)) * K + k0 + (seg << 3);
            cp16z(sA + (uint32_t)(r * LDH + (seg << 3)) * 2u, gp,
                  gr < M ? 16u : 0u);
        }
#pragma unroll
        for (int j = 0; j < 8; j++) {           // 2048 segs
            int id = tid + (j << 8);
            int r = id >> 3, seg = id & 7;
            const __half* gp = Bw + (size_t)(n0 + r) * K + k0 + (seg << 3);
            cp16(sB + (uint32_t)(r * LDH + (seg << 3)) * 2u, gp);
        }
        asm volatile("cp.async.commit_group;" ::: "memory");
    };

    float acc[4][8][4];
#pragma unroll
    for (int i = 0; i < 4; i++)
#pragma unroll
        for (int j = 0; j < 8; j++)
#pragma unroll
            for (int r = 0; r < 4; r++) acc[i][j][r] = 0.f;

    load_chunk(0, 0);
    if (NC > 1) load_chunk(1, 1);

    // LDSM lane base offsets (bytes, within a stage)
    const uint32_t aOff =
        ((uint32_t)(wm * 64 + (lane & 15)) * LDH + (uint32_t)((lane >> 4) << 3)) * 2u;
    const uint32_t bOff =
        ((uint32_t)(wn * 64 + (((lane >> 3) >> 1) << 3) + (lane & 7)) * LDH
         + (uint32_t)(((lane >> 3) & 1) << 3)) * 2u;

    uint32_t af[2][4][4], bf[2][4][4];
    for (int c = 0; c < NC; c++) {
        if (c + 1 < NC)
            asm volatile("cp.async.wait_group 1;" ::: "memory");
        else
            asm volatile("cp.async.wait_group 0;" ::: "memory");
        __syncthreads();   // chunk c visible; all warps done reading c-1

        const int st = c % 3;
        const uint32_t aBase = sb + st * STG + aOff;
        const uint32_t bBase = sb + st * STG + ASTG + bOff;

        // prime k-step 0 fragments
#pragma unroll
        for (int mt = 0; mt < 4; mt++)
            ldsm_x4(af[0][mt], aBase + (uint32_t)(mt * 16 * LDH) * 2u);
#pragma unroll
        for (int g = 0; g < 4; g++)
            ldsm_x4(bf[0][g], bBase + (uint32_t)(g * 16 * LDH) * 2u);

#pragma unroll
        for (int s = 0; s < 4; s++) {           // 4 k-steps of 16
            const int cur = s & 1, nxt = cur ^ 1;
            if (s < 3) {                        // prefetch fragments for s+1
                const uint32_t ks = (uint32_t)(s + 1) * 32u;
#pragma unroll
                for (int mt = 0; mt < 4; mt++)
                    ldsm_x4(af[nxt][mt], aBase + ks + (uint32_t)(mt * 16 * LDH) * 2u);
#pragma unroll
                for (int g = 0; g < 4; g++)
                    ldsm_x4(bf[nxt][g], bBase + ks + (uint32_t)(g * 16 * LDH) * 2u);
            }
#pragma unroll
            for (int mt = 0; mt < 4; mt++)
#pragma unroll
                for (int g = 0; g < 4; g++) {
                    mma_f16(acc[mt][2 * g], af[cur][mt], &bf[cur][g][0]);
                    mma_f16(acc[mt][2 * g + 1], af[cur][mt], &bf[cur][g][2]);
                }
        }
        // prefetch chunk c+2 into the stage just freed
        if (c + 2 < NC) load_chunk(c + 2, (c + 2) % 3);
    }

    // epilogue (nt-outer): bias (+relu) (+stats shfl-reduce), stores
    const int qr = lane >> 2, qc = lane & 3;
#pragma unroll
    for (int nt = 0; nt < 8; nt++) {
        const int cc = wn * 64 + nt * 8 + qc * 2;
        const float b0 = s_bias[cc], b1 = s_bias[cc + 1];
        float s0 = 0.f, s1 = 0.f, q0 = 0.f, q1 = 0.f;
#pragma unroll
        for (int mt = 0; mt < 4; mt++) {
            int r0 = row0 + wm * 64 + mt * 16 + qr;
            bool ok0 = r0 < M, ok2 = r0 + 8 < M;
            float v0 = acc[mt][nt][0] + b0, v1 = acc[mt][nt][1] + b1;
            float v2 = acc[mt][nt][2] + b0, v3 = acc[mt][nt][3] + b1;
            if (RELU) {
                v0 = fmaxf(v0, 0.f); v1 = fmaxf(v1, 0.f);
                v2 = fmaxf(v2, 0.f); v3 = fmaxf(v3, 0.f);
            }
            if (STATS) {
                if (ok0) {
                    s0 += v0; s1 += v1;
                    q0 = fmaf(v0, v0, q0); q1 = fmaf(v1, v1, q1);
                }
                if (ok2) {
                    s0 += v2; s1 += v3;
                    q0 = fmaf(v2, v2, q0); q1 = fmaf(v3, v3, q1);
                }
            }
            if (OUT_HALF) {
                __half* C = (__half*)Cv;
                if (ok0)
                    *(__half2*)(C + (size_t)r0 * N + n0 + cc) = __floats2half2_rn(v0, v1);
                if (ok2)
                    *(__half2*)(C + (size_t)(r0 + 8) * N + n0 + cc) = __floats2half2_rn(v2, v3);
            } else {
                float* C = (float*)Cv;
                if (ok0)
                    *(float2*)(C + (size_t)r0 * N + n0 + cc) = make_float2(v0, v1);
                if (ok2)
                    *(float2*)(C + (size_t)(r0 + 8) * N + n0 + cc) = make_float2(v2, v3);
            }
        }
        if (STATS) {
            // reduce over the 8 quad-rows (lanes differing in bits 2..4)
#pragma unroll
            for (int off = 4; off <= 16; off <<= 1) {
                s0 += __shfl_xor_sync(0xffffffffu, s0, off);
                s1 += __shfl_xor_sync(0xffffffffu, s1, off);
                q0 += __shfl_xor_sync(0xffffffffu, q0, off);
                q1 += __shfl_xor_sync(0xffffffffu, q1, off);
            }
            if (qr == 0) {
                float* gs = g_stats + (size_t)(blockIdx.y & (NCOPY - 1)) * 512;
                atomicAdd(gs + cc, s0);
                atomicAdd(gs + cc + 1, s1);
                atomicAdd(gs + 256 + cc, q0);
                atomicAdd(gs + 256 + cc + 1, q1);
            }
        }
    }
}

// ---------------- K3: finalize BN statistics ---------------------------------
__global__ __launch_bounds__(256) void k_finstats(const float* __restrict__ bg,
                                                  const float* __restrict__ bb) {
    int o = threadIdx.x;
    float s = 0.f, s2 = 0.f;
#pragma unroll 8
    for (int c = 0; c < NCOPY; c++) {
        s += g_stats[c * 512 + o];
        s2 += g_stats[c * 512 + 256 + o];
    }
    const float inv = 1.f / (float)R_ROWS;
    float mu = s * inv;
    float var = fmaxf(s2 * inv - mu * mu, 0.f);
    float rs = rsqrtf(var + 1e-5f);
    float sc = rs * bg[o];
    g_sc[o] = sc;
    g_tsh[o] = bb[o] - mu * sc;
}

// ---------------- K4: BN apply + LayerNorm (h half -> hn half) ---------------
__global__ __launch_bounds__(256) void k_bnln(const float* __restrict__ lg,
                                              const float* __restrict__ lb) {
    int row = blockIdx.x * 8 + (threadIdx.x >> 5);
    int lane = threadIdx.x & 31;
    const __half2* hp = (const __half2*)(g_hh + (size_t)row * 256);
    float v[8];
    float s = 0.f, s2 = 0.f;
#pragma unroll
    for (int i = 0; i < 4; i++) {
        int k2 = lane + 32 * i;                 // half2 index (0..127)
        float2 xv = __half22float2(hp[k2]);
        float x0 = fmaf(xv.x, g_sc[2 * k2], g_tsh[2 * k2]);
        float x1 = fmaf(xv.y, g_sc[2 * k2 + 1], g_tsh[2 * k2 + 1]);
        v[2 * i] = x0; v[2 * i + 1] = x1;
        s += x0 + x1;
        s2 = fmaf(x0, x0, s2);
        s2 = fmaf(x1, x1, s2);
    }
#pragma unroll
    for (int off = 16; off; off >>= 1) {
        s += __shfl_xor_sync(0xffffffffu, s, off);
        s2 += __shfl_xor_sync(0xffffffffu, s2, off);
    }
    float mu = s * (1.f / 256.f);
    float var = fmaxf(s2 * (1.f / 256.f) - mu * mu, 0.f);
    float rs = rsqrtf(var + 1e-5f);
    __half2* op = (__half2*)(g_hn + (size_t)row * 256);
#pragma unroll
    for (int i = 0; i < 4; i++) {
        int k2 = lane + 32 * i;
        float y0 = fmaf((v[2 * i] - mu) * rs, lg[2 * k2], lb[2 * k2]);
        float y1 = fmaf((v[2 * i + 1] - mu) * rs, lg[2 * k2 + 1], lb[2 * k2 + 1]);
        op[k2] = __floats2half2_rn(y0, y1);
    }
}

// ---------------- host side --------------------------------------------------
extern "C" void kernel_launch(void* const* d_in, const int* in_sizes, int n_in,
                              void* d_out, int out_size) {
    (void)in_sizes; (void)n_in; (void)out_size;
    const float* x   = (const float*)d_in[0];
    const float* adj = (const float*)d_in[1];
    const float* w1  = (const float*)d_in[2];
    const float* b1  = (const float*)d_in[3];
    const float* w2  = (const float*)d_in[4];
    const float* b2  = (const float*)d_in[5];
    const float* bng = (const float*)d_in[6];
    const float* bnb = (const float*)d_in[7];
    const float* lng = (const float*)d_in[8];
    const float* lnb = (const float*)d_in[9];
    const float* mw1 = (const float*)d_in[10];
    const float* mb1 = (const float*)d_in[11];
    const float* mw2 = (const float*)d_in[12];
    const float* mb2 = (const float*)d_in[13];
    float* out = (float*)d_out;

    void *pxm = 0, *phh = 0, *phn = 0, *pm = 0, *pWc = 0, *pW1 = 0, *pW2 = 0, *pbc = 0;
    cudaGetSymbolAddress(&pxm, g_xm);
    cudaGetSymbolAddress(&phh, g_hh);
    cudaGetSymbolAddress(&phn, g_hn);
    cudaGetSymbolAddress(&pm, g_midh);
    cudaGetSymbolAddress(&pWc, g_Wch);
    cudaGetSymbolAddress(&pW1, g_W1h);
    cudaGetSymbolAddress(&pW2, g_W2h);
    cudaGetSymbolAddress(&pbc, g_bc);

    cudaFuncSetAttribute(k_mma<true, true, true>,
                         cudaFuncAttributeMaxDynamicSharedMemorySize, SMEM_DYN);
    cudaFuncSetAttribute(k_mma<true, true, false>,
                         cudaFuncAttributeMaxDynamicSharedMemorySize, SMEM_DYN);
    cudaFuncSetAttribute(k_mma<false, false, false>,
                         cudaFuncAttributeMaxDynamicSharedMemorySize, SMEM_DYN);

    k_prep<<<512, 256>>>(w1, b1, w2, b2, mw1, mw2);
    // xm = adj @ x (per frame), half
    k_xmix<<<R_ROWS / 17, 256>>>(x, adj);
    // h (half) = relu(xm @ Wc^T + bc) + BN partial stats (shfl + striped atomics)
    k_mma<true, true, true><<<dim3(1, MTILES), 256, SMEM_DYN>>>(
        (const __half*)pxm, (const __half*)pWc, (const float*)pbc,
        (void*)phh, R_ROWS, 256, 256);
    k_finstats<<<1, 256>>>(bng, bnb);
    // hn (half) = LN(BN(h))
    k_bnln<<<R_ROWS / 8, 256>>>(lng, lnb);
    // mid (half) = relu(hn @ mlp_w1^T + mb1)
    k_mma<true, true, false><<<dim3(2, MTILES), 256, SMEM_DYN>>>(
        (const __half*)phn, (const __half*)pW1, mb1, (void*)pm, R_ROWS, 512, 256);
    // out (fp32) = mid @ mlp_w2^T + mb2
    k_mma<false, false, false><<<dim3(1, MTILES), 256, SMEM_DYN>>>(
        (const __half*)pm, (const __half*)pW2, mb2, (void*)out, R_ROWS, 256, 512);
}

// round 15
// speedup vs baseline: 1.4470x; 1.0238x over previous
#include <cuda_runtime.h>
#include <cuda_fp16.h>
#include <cstdint>

#define R_ROWS 264384                    // B*L*J = 64*243*17
#define NCOPY  64                        // striped BN accumulator copies
#define MTILES ((R_ROWS + 127) / 128)    // 2066

// ---------------- scratch (device globals: no allocations allowed) ----------
__device__ __half g_xm[(long long)R_ROWS * 256];    // adj-mixed x (half)
__device__ __half g_hh[(long long)R_ROWS * 256];    // h = relu(xm@Wc+bc) (half)
__device__ __half g_hn[(long long)R_ROWS * 256];    // LN output (half)
__device__ __half g_midh[(long long)R_ROWS * 512];  // MLP hidden (half)
__device__ __half g_Wch[256 * 256];                 // h(w1+w2)   [o][d] K-major
__device__ __half g_W1h[512 * 256];                 // h(mlp_w1)  [h][o] K-major
__device__ __half g_W2h[256 * 512];                 // h(mlp_w2)  [o][h] K-major
__device__ float  g_bc[256];                        // b1+b2
__device__ float  g_stats[NCOPY * 512];             // [sum|sumsq] per copy
__device__ float  g_sc[256];                        // BN scale
__device__ float  g_tsh[256];                       // BN shift

// ---------------- helpers ----------------------------------------------------
__device__ __forceinline__ uint32_t smem_u32(const void* p) {
    uint32_t a;
    asm("{ .reg .u64 t; cvta.to.shared.u64 t, %1; cvt.u32.u64 %0, t; }"
        : "=r"(a) : "l"(p));
    return a;
}
__device__ __forceinline__ void mma_f16(float* d, const uint32_t* a, const uint32_t* b) {
    asm volatile(
        "mma.sync.aligned.m16n8k16.row.col.f32.f16.f16.f32 "
        "{%0,%1,%2,%3}, {%4,%5,%6,%7}, {%8,%9}, {%0,%1,%2,%3};\n"
        : "+f"(d[0]), "+f"(d[1]), "+f"(d[2]), "+f"(d[3])
        : "r"(a[0]), "r"(a[1]), "r"(a[2]), "r"(a[3]), "r"(b[0]), "r"(b[1]));
}
__device__ __forceinline__ void ldsm_x4(uint32_t* r, uint32_t addr) {
    asm volatile("ldmatrix.sync.aligned.m8n8.x4.shared.b16 {%0,%1,%2,%3}, [%4];"
                 : "=r"(r[0]), "=r"(r[1]), "=r"(r[2]), "=r"(r[3]) : "r"(addr));
}
__device__ __forceinline__ void cp16(uint32_t dst, const void* src) {
    asm volatile("cp.async.cg.shared.global [%0], [%1], 16;" :: "r"(dst), "l"(src));
}
__device__ __forceinline__ void cp16z(uint32_t dst, const void* src, unsigned pred16) {
    asm volatile("cp.async.cg.shared.global [%0], [%1], 16, %2;"
                 :: "r"(dst), "l"(src), "r"(pred16));
}

// ---------------- K0: weight prep (half) + stats zeroing ---------------------
__global__ __launch_bounds__(256) void k_prep(
        const float* __restrict__ w1, const float* __restrict__ b1,
        const float* __restrict__ w2, const float* __restrict__ b2,
        const float* __restrict__ mw1, const float* __restrict__ mw2) {
    int i = blockIdx.x * 256 + threadIdx.x;   // 0..131071
    g_W1h[i] = __float2half_rn(mw1[i]);       // native [512,256] K-major
    g_W2h[i] = __float2half_rn(mw2[i]);       // native [256,512] K-major
    if (i < 256 * 256) g_Wch[i] = __float2half_rn(w1[i] + w2[i]);
    if (i < NCOPY * 512) g_stats[i] = 0.f;
    if (i < 256) g_bc[i] = b1[i] + b2[i];
}

// ---------------- K1: per-frame adjacency mix on x, fp32 -> half -------------
__global__ __launch_bounds__(256) void k_xmix(const float* __restrict__ x,
                                              const float* __restrict__ adj) {
    __shared__ float sadj[17 * 17];
    int f = blockIdx.x;
    int o = threadIdx.x;
    for (int i = o; i < 289; i += 256) sadj[i] = adj[i];
    __syncthreads();
    const float* xp = x + (size_t)f * 17 * 256 + o;
    float v[17];
#pragma unroll
    for (int j = 0; j < 17; j++) v[j] = xp[(size_t)j * 256];
    __half* op = g_xm + (size_t)f * 17 * 256 + o;
#pragma unroll
    for (int i = 0; i < 17; i++) {
        float g = 0.f;
#pragma unroll
        for (int j = 0; j < 17; j++) g = fmaf(sadj[i * 17 + j], v[j], g);
        op[(size_t)i * 256] = __float2half_rn(g);
    }
}

// ---------- fp16 mma GEMM: C[M,N] = A[M,K] @ Bw[N,K]^T + bias ----------------
// CTA 128x128, BK=64 (4 k16-steps), 256 thr (8 warps: 2M x 4N), warp 64x32.
// 3-stage cp.async pipeline, 2 CTAs/SM (4 warps/SMSP for latency coverage).
// STATS: nt-outer epilogue, shfl-reduced sums -> striped global atomics.
#define LDH   72                          // 64 halves + 8 pad
#define ASTG  (128 * LDH * 2)             // 18432 B
#define BSTG  (128 * LDH * 2)             // 18432 B
#define STG   (ASTG + BSTG)               // 36864 B
#define SMEM_DYN (3 * STG)                // 110592 B

template <bool RELU, bool OUT_HALF, bool STATS>
__global__ __launch_bounds__(256, 2) void k_mma(
        const __half* __restrict__ A, const __half* __restrict__ Bw,
        const float* __restrict__ bias, void* __restrict__ Cv,
        int M, int N, int K) {
    extern __shared__ char dsm[];
    __shared__ float s_bias[128];

    const int tid = threadIdx.x;
    const int wid = tid >> 5, lane = tid & 31;
    const int wm = wid >> 2, wn = wid & 3;      // warp grid 2x4
    const int row0 = blockIdx.y * 128;
    const int n0 = blockIdx.x * 128;
    const int NC = K >> 6;                      // 64-wide chunks

    const uint32_t sb = smem_u32(dsm);

    if (tid < 128) s_bias[tid] = bias[n0 + tid];

    // chunk loader: A 128 rows x 64 halves (8 x 16B segs), B 128 rows x 8 segs
    auto load_chunk = [&](int ck, int st) {
        const int k0 = ck << 6;
        const uint32_t sA = sb + (uint32_t)st * STG;
        const uint32_t sB = sA + ASTG;
#pragma unroll
        for (int j = 0; j < 4; j++) {           // 1024 segs
            int id = tid + (j << 8);
            int r = id >> 3, seg = id & 7;
            int gr = row0 + r;
            const __half* gp =
                A + (size_t)(gr < M ? gr : (M - 1)) * K + k0 + (seg << 3);
            cp16z(sA + (uint32_t)(r * LDH + (seg << 3)) * 2u, gp,
                  gr < M ? 16u : 0u);
        }
#pragma unroll
        for (int j = 0; j < 4; j++) {           // 1024 segs
            int id = tid + (j << 8);
            int r = id >> 3, seg = id & 7;
            const __half* gp = Bw + (size_t)(n0 + r) * K + k0 + (seg << 3);
            cp16(sB + (uint32_t)(r * LDH + (seg << 3)) * 2u, gp);
        }
        asm volatile("cp.async.commit_group;" ::: "memory");
    };

    float acc[4][4][4];
#pragma unroll
    for (int i = 0; i < 4; i++)
#pragma unroll
        for (int j = 0; j < 4; j++)
#pragma unroll
            for (int r = 0; r < 4; r++) acc[i][j][r] = 0.f;

    load_chunk(0, 0);
    if (NC > 1) load_chunk(1, 1);

    // LDSM lane base offsets (bytes, within a stage)
    const uint32_t aOff =
        ((uint32_t)(wm * 64 + (lane & 15)) * LDH + (uint32_t)((lane >> 4) << 3)) * 2u;
    const uint32_t bOff =
        ((uint32_t)(wn * 32 + (((lane >> 3) >> 1) << 3) + (lane & 7)) * LDH
         + (uint32_t)(((lane >> 3) & 1) << 3)) * 2u;

    for (int c = 0; c < NC; c++) {
        if (c + 1 < NC)
            asm volatile("cp.async.wait_group 1;" ::: "memory");
        else
            asm volatile("cp.async.wait_group 0;" ::: "memory");
        __syncthreads();   // chunk c visible; all warps done reading c-1

        const int st = c % 3;
        const uint32_t aBase = sb + st * STG + aOff;
        const uint32_t bBase = sb + st * STG + ASTG + bOff;

#pragma unroll
        for (int s = 0; s < 4; s++) {           // 4 k-steps of 16
            const uint32_t ks = (uint32_t)s * 32u;
            uint32_t af[4][4], bf[2][4];        // bf[g] covers nt 2g, 2g+1
#pragma unroll
            for (int mt = 0; mt < 4; mt++)
                ldsm_x4(af[mt], aBase + ks + (uint32_t)(mt * 16 * LDH) * 2u);
#pragma unroll
            for (int g = 0; g < 2; g++)
                ldsm_x4(bf[g], bBase + ks + (uint32_t)(g * 16 * LDH) * 2u);
#pragma unroll
            for (int mt = 0; mt < 4; mt++)
#pragma unroll
                for (int g = 0; g < 2; g++) {
                    mma_f16(acc[mt][2 * g], af[mt], &bf[g][0]);
                    mma_f16(acc[mt][2 * g + 1], af[mt], &bf[g][2]);
                }
        }
        // prefetch chunk c+2 into the stage just freed
        if (c + 2 < NC) load_chunk(c + 2, (c + 2) % 3);
    }

    // epilogue (nt-outer): bias (+relu) (+stats shfl-reduce), stores
    const int qr = lane >> 2, qc = lane & 3;
#pragma unroll
    for (int nt = 0; nt < 4; nt++) {
        const int cc = wn * 32 + nt * 8 + qc * 2;
        const float b0 = s_bias[cc], b1 = s_bias[cc + 1];
        float s0 = 0.f, s1 = 0.f, q0 = 0.f, q1 = 0.f;
#pragma unroll
        for (int mt = 0; mt < 4; mt++) {
            int r0 = row0 + wm * 64 + mt * 16 + qr;
            bool ok0 = r0 < M, ok2 = r0 + 8 < M;
            float v0 = acc[mt][nt][0] + b0, v1 = acc[mt][nt][1] + b1;
            float v2 = acc[mt][nt][2] + b0, v3 = acc[mt][nt][3] + b1;
            if (RELU) {
                v0 = fmaxf(v0, 0.f); v1 = fmaxf(v1, 0.f);
                v2 = fmaxf(v2, 0.f); v3 = fmaxf(v3, 0.f);
            }
            if (STATS) {
                if (ok0) {
                    s0 += v0; s1 += v1;
                    q0 = fmaf(v0, v0, q0); q1 = fmaf(v1, v1, q1);
                }
                if (ok2) {
                    s0 += v2; s1 += v3;
                    q0 = fmaf(v2, v2, q0); q1 = fmaf(v3, v3, q1);
                }
            }
            if (OUT_HALF) {
                __half* C = (__half*)Cv;
                if (ok0)
                    *(__half2*)(C + (size_t)r0 * N + n0 + cc) = __floats2half2_rn(v0, v1);
                if (ok2)
                    *(__half2*)(C + (size_t)(r0 + 8) * N + n0 + cc) = __floats2half2_rn(v2, v3);
            } else {
                float* C = (float*)Cv;
                if (ok0)
                    *(float2*)(C + (size_t)r0 * N + n0 + cc) = make_float2(v0, v1);
                if (ok2)
                    *(float2*)(C + (size_t)(r0 + 8) * N + n0 + cc) = make_float2(v2, v3);
            }
        }
        if (STATS) {
            // reduce over the 8 quad-rows (lanes differing in bits 2..4)
#pragma unroll
            for (int off = 4; off <= 16; off <<= 1) {
                s0 += __shfl_xor_sync(0xffffffffu, s0, off);
                s1 += __shfl_xor_sync(0xffffffffu, s1, off);
                q0 += __shfl_xor_sync(0xffffffffu, q0, off);
                q1 += __shfl_xor_sync(0xffffffffu, q1, off);
            }
            if (qr == 0) {
                float* gs = g_stats + (size_t)(blockIdx.y & (NCOPY - 1)) * 512;
                atomicAdd(gs + n0 + cc, s0);
                atomicAdd(gs + n0 + cc + 1, s1);
                atomicAdd(gs + 256 + n0 + cc, q0);
                atomicAdd(gs + 256 + n0 + cc + 1, q1);
            }
        }
    }
}

// ---------------- K3: finalize BN statistics ---------------------------------
__global__ __launch_bounds__(256) void k_finstats(const float* __restrict__ bg,
                                                  const float* __restrict__ bb) {
    int o = threadIdx.x;
    float s = 0.f, s2 = 0.f;
#pragma unroll 8
    for (int c = 0; c < NCOPY; c++) {
        s += g_stats[c * 512 + o];
        s2 += g_stats[c * 512 + 256 + o];
    }
    const float inv = 1.f / (float)R_ROWS;
    float mu = s * inv;
    float var = fmaxf(s2 * inv - mu * mu, 0.f);
    float rs = rsqrtf(var + 1e-5f);
    float sc = rs * bg[o];
    g_sc[o] = sc;
    g_tsh[o] = bb[o] - mu * sc;
}

// ---------------- K4: BN apply + LayerNorm (h half -> hn half) ---------------
__global__ __launch_bounds__(256) void k_bnln(const float* __restrict__ lg,
                                              const float* __restrict__ lb) {
    int row = blockIdx.x * 8 + (threadIdx.x >> 5);
    int lane = threadIdx.x & 31;
    const __half2* hp = (const __half2*)(g_hh + (size_t)row * 256);
    float v[8];
    float s = 0.f, s2 = 0.f;
#pragma unroll
    for (int i = 0; i < 4; i++) {
        int k2 = lane + 32 * i;                 // half2 index (0..127)
        float2 xv = __half22float2(hp[k2]);
        float x0 = fmaf(xv.x, g_sc[2 * k2], g_tsh[2 * k2]);
        float x1 = fmaf(xv.y, g_sc[2 * k2 + 1], g_tsh[2 * k2 + 1]);
        v[2 * i] = x0; v[2 * i + 1] = x1;
        s += x0 + x1;
        s2 = fmaf(x0, x0, s2);
        s2 = fmaf(x1, x1, s2);
    }
#pragma unroll
    for (int off = 16; off; off >>= 1) {
        s += __shfl_xor_sync(0xffffffffu, s, off);
        s2 += __shfl_xor_sync(0xffffffffu, s2, off);
    }
    float mu = s * (1.f / 256.f);
    float var = fmaxf(s2 * (1.f / 256.f) - mu * mu, 0.f);
    float rs = rsqrtf(var + 1e-5f);
    __half2* op = (__half2*)(g_hn + (size_t)row * 256);
#pragma unroll
    for (int i = 0; i < 4; i++) {
        int k2 = lane + 32 * i;
        float y0 = fmaf((v[2 * i] - mu) * rs, lg[2 * k2], lb[2 * k2]);
        float y1 = fmaf((v[2 * i + 1] - mu) * rs, lg[2 * k2 + 1], lb[2 * k2 + 1]);
        op[k2] = __floats2half2_rn(y0, y1);
    }
}

// ---------------- host side --------------------------------------------------
extern "C" void kernel_launch(void* const* d_in, const int* in_sizes, int n_in,
                              void* d_out, int out_size) {
    (void)in_sizes; (void)n_in; (void)out_size;
    const float* x   = (const float*)d_in[0];
    const float* adj = (const float*)d_in[1];
    const float* w1  = (const float*)d_in[2];
    const float* b1  = (const float*)d_in[3];
    const float* w2  = (const float*)d_in[4];
    const float* b2  = (const float*)d_in[5];
    const float* bng = (const float*)d_in[6];
    const float* bnb = (const float*)d_in[7];
    const float* lng = (const float*)d_in[8];
    const float* lnb = (const float*)d_in[9];
    const float* mw1 = (const float*)d_in[10];
    const float* mb1 = (const float*)d_in[11];
    const float* mw2 = (const float*)d_in[12];
    const float* mb2 = (const float*)d_in[13];
    float* out = (float*)d_out;

    void *pxm = 0, *phh = 0, *phn = 0, *pm = 0, *pWc = 0, *pW1 = 0, *pW2 = 0, *pbc = 0;
    cudaGetSymbolAddress(&pxm, g_xm);
    cudaGetSymbolAddress(&phh, g_hh);
    cudaGetSymbolAddress(&phn, g_hn);
    cudaGetSymbolAddress(&pm, g_midh);
    cudaGetSymbolAddress(&pWc, g_Wch);
    cudaGetSymbolAddress(&pW1, g_W1h);
    cudaGetSymbolAddress(&pW2, g_W2h);
    cudaGetSymbolAddress(&pbc, g_bc);

    cudaFuncSetAttribute(k_mma<true, true, true>,
                         cudaFuncAttributeMaxDynamicSharedMemorySize, SMEM_DYN);
    cudaFuncSetAttribute(k_mma<true, true, false>,
                         cudaFuncAttributeMaxDynamicSharedMemorySize, SMEM_DYN);
    cudaFuncSetAttribute(k_mma<false, false, false>,
                         cudaFuncAttributeMaxDynamicSharedMemorySize, SMEM_DYN);

    k_prep<<<512, 256>>>(w1, b1, w2, b2, mw1, mw2);
    // xm = adj @ x (per frame), half
    k_xmix<<<R_ROWS / 17, 256>>>(x, adj);
    // h (half) = relu(xm @ Wc^T + bc) + BN partial stats (shfl + striped atomics)
    k_mma<true, true, true><<<dim3(2, MTILES), 256, SMEM_DYN>>>(
        (const __half*)pxm, (const __half*)pWc, (const float*)pbc,
        (void*)phh, R_ROWS, 256, 256);
    k_finstats<<<1, 256>>>(bng, bnb);
    // hn (half) = LN(BN(h))
    k_bnln<<<R_ROWS / 8, 256>>>(lng, lnb);
    // mid (half) = relu(hn @ mlp_w1^T + mb1)
    k_mma<true, true, false><<<dim3(4, MTILES), 256, SMEM_DYN>>>(
        (const __half*)phn, (const __half*)pW1, mb1, (void*)pm, R_ROWS, 512, 256);
    // out (fp32) = mid @ mlp_w2^T + mb2
    k_mma<false, false, false><<<dim3(2, MTILES), 256, SMEM_DYN>>>(
        (const __half*)pm, (const __half*)pW2, mb2, (void*)out, R_ROWS, 256, 512);
}